// round 7
// baseline (speedup 1.0000x reference)
#include <cuda_runtime.h>
#include <cuda_bf16.h>
#include <stdint.h>

// ---------------- problem constants (static shapes) ----------------
#define N_OV 20000
#define N_OF 30000
#define N_SV 4000
#define N_SF 5000
#define NSAMP 50
#define N_SAMPLES 250000
// vertex grid (reverse term)
#define GRID_G 64
#define NCELLS (GRID_G * GRID_G * GRID_G)     // 262144
#define SCAN_BLOCKS 256                        // 256 * 1024
// barycenter grid (forward term)
#define GRID_G2 32
#define NCELLS2 (GRID_G2 * GRID_G2 * GRID_G2)  // 32768
#define SCAN_BLOCKS2 32                         // 32 * 1024
#define REV_BLOCKS 977                          // ceil(250000/256)
#define FWD_BLOCKS 20                           // ceil(5000/256) -> 20*256=5120

// ---------------- device scratch (static, no runtime alloc) ----------------
__device__ float4    g_obp[N_OF];             // (bx,by,bz,|b|^2) original barycenters
__device__ float4    g_sb[N_SF];              // (bx,by,bz,|b|^2) simplified barycenters
__device__ unsigned  g_minfwd[N_SF];          // forward d2 bits (direct write)
__device__ float4    g_samples[N_SAMPLES];    // (x,y,z,|p|^2)
__device__ unsigned  g_maxbits;
__device__ double    g_part[REV_BLOCKS];
// grid V (vertices)
__device__ unsigned  g_bbox[6];
__device__ int       g_count[NCELLS];
__device__ int       g_cursor[NCELLS];
__device__ int       g_cellstart[NCELLS + 1];
__device__ int       g_blocksum[SCAN_BLOCKS];
__device__ int       g_blockoff[SCAN_BLOCKS];
__device__ float4    g_sorted[N_OV];          // (x,y,z,|v|^2)
// grid B (original barycenters)
__device__ unsigned  g_bbox2[6];
__device__ int       g_count2[NCELLS2];
__device__ int       g_cursor2[NCELLS2];
__device__ int       g_cellstart2[NCELLS2 + 1];
__device__ int       g_blocksum2[SCAN_BLOCKS2];
__device__ int       g_blockoff2[SCAN_BLOCKS2];
__device__ float4    g_sorted2[N_OF];         // (bx,by,bz,|b|^2)

// ---------------- ordered-float helpers ----------------
__device__ __forceinline__ unsigned f2o(float f) {
    unsigned u = __float_as_uint(f);
    return (u & 0x80000000u) ? ~u : (u | 0x80000000u);
}
__device__ __forceinline__ float o2f(unsigned u) {
    u = (u & 0x80000000u) ? (u & 0x7fffffffu) : ~u;
    return __uint_as_float(u);
}

// ---------------- threefry2x32 (JAX partitionable, 20 rounds) ----------------
__device__ __forceinline__ uint32_t rotl32(uint32_t x, int r) {
    return (x << r) | (x >> (32 - r));
}
__device__ __forceinline__ void threefry2x32(uint32_t k0, uint32_t k1,
                                             uint32_t x0, uint32_t x1,
                                             uint32_t& o0, uint32_t& o1) {
    uint32_t ks0 = k0, ks1 = k1, ks2 = k0 ^ k1 ^ 0x1BD11BDAu;
    x0 += ks0; x1 += ks1;
    x0 += x1; x1 = rotl32(x1, 13); x1 ^= x0;
    x0 += x1; x1 = rotl32(x1, 15); x1 ^= x0;
    x0 += x1; x1 = rotl32(x1, 26); x1 ^= x0;
    x0 += x1; x1 = rotl32(x1,  6); x1 ^= x0;
    x0 += ks1; x1 += ks2 + 1u;
    x0 += x1; x1 = rotl32(x1, 17); x1 ^= x0;
    x0 += x1; x1 = rotl32(x1, 29); x1 ^= x0;
    x0 += x1; x1 = rotl32(x1, 16); x1 ^= x0;
    x0 += x1; x1 = rotl32(x1, 24); x1 ^= x0;
    x0 += ks2; x1 += ks0 + 2u;
    x0 += x1; x1 = rotl32(x1, 13); x1 ^= x0;
    x0 += x1; x1 = rotl32(x1, 15); x1 ^= x0;
    x0 += x1; x1 = rotl32(x1, 26); x1 ^= x0;
    x0 += x1; x1 = rotl32(x1,  6); x1 ^= x0;
    x0 += ks0; x1 += ks1 + 3u;
    x0 += x1; x1 = rotl32(x1, 17); x1 ^= x0;
    x0 += x1; x1 = rotl32(x1, 29); x1 ^= x0;
    x0 += x1; x1 = rotl32(x1, 16); x1 ^= x0;
    x0 += x1; x1 = rotl32(x1, 24); x1 ^= x0;
    x0 += ks1; x1 += ks2 + 4u;
    x0 += x1; x1 = rotl32(x1, 13); x1 ^= x0;
    x0 += x1; x1 = rotl32(x1, 15); x1 ^= x0;
    x0 += x1; x1 = rotl32(x1, 26); x1 ^= x0;
    x0 += x1; x1 = rotl32(x1,  6); x1 ^= x0;
    x0 += ks2; x1 += ks0 + 5u;
    o0 = x0; o1 = x1;
}
__device__ __forceinline__ float bits_to_uniform(uint32_t bits) {
    return __uint_as_float((bits >> 9) | 0x3f800000u) - 1.0f;
}

// ---------------- grid geometry ----------------
struct GridGeom { float x0, y0, z0, invh, h; };
__device__ __forceinline__ GridGeom load_geom(const unsigned* bbox, int G) {
    GridGeom g;
    g.x0 = o2f(bbox[0]); g.y0 = o2f(bbox[1]); g.z0 = o2f(bbox[2]);
    float ex = o2f(bbox[3]) - g.x0;
    float ey = o2f(bbox[4]) - g.y0;
    float ez = o2f(bbox[5]) - g.z0;
    float e = fmaxf(fmaxf(ex, ey), fmaxf(ez, 1e-20f));
    g.h = e / (float)G;
    g.invh = (float)G / e;
    return g;
}
__device__ __forceinline__ int cell_coord(float v, float v0, float invh, int G) {
    int c = (int)((v - v0) * invh);
    return min(max(c, 0), G - 1);
}

// ---------------- exact expanding-shell 1-NN (returns d^2) ----------------
template <int G>
__device__ __forceinline__ float shell_nn(float qx, float qy, float qz, float qw,
                                          const GridGeom g,
                                          const int* __restrict__ cellstart,
                                          const float4* __restrict__ sorted) {
    float m2x = -2.0f * qx, m2y = -2.0f * qy, m2z = -2.0f * qz;
    int cx = cell_coord(qx, g.x0, g.invh, G);
    int cy = cell_coord(qy, g.y0, g.invh, G);
    int cz = cell_coord(qz, g.z0, g.invh, G);

    float best = 3.0e38f;   // best t, d2 = t + qw
    for (int R = 0; R <= G; R++) {
        if (R > 0) {
            float lb = (float)(R - 1) * g.h;
            if (best + qw <= lb * lb) break;
        }
        int zlo = max(cz - R, 0), zhi = min(cz + R, G - 1);
        int ylo = max(cy - R, 0), yhi = min(cy + R, G - 1);
        int xlo = max(cx - R, 0), xhi = min(cx + R, G - 1);
        for (int z = zlo; z <= zhi; z++) {
            bool ze = (z == cz - R) || (z == cz + R);
            for (int y = ylo; y <= yhi; y++) {
                bool edge = ze || (y == cy - R) || (y == cy + R);
                int rowbase = (z * G + y) * G;
                if (edge) {
                    int p0 = __ldg(&cellstart[rowbase + xlo]);
                    int p1 = __ldg(&cellstart[rowbase + xhi + 1]);
                    for (int p = p0; p < p1; p++) {
                        float4 v = sorted[p];
                        float t = fmaf(v.x, m2x, fmaf(v.y, m2y, fmaf(v.z, m2z, v.w)));
                        best = fminf(best, t);
                    }
                } else {
                    int xa = cx - R, xb = cx + R;
                    if (xa >= 0) {
                        int c0 = rowbase + xa;
                        int p0 = __ldg(&cellstart[c0]), p1 = __ldg(&cellstart[c0 + 1]);
                        for (int p = p0; p < p1; p++) {
                            float4 v = sorted[p];
                            float t = fmaf(v.x, m2x, fmaf(v.y, m2y, fmaf(v.z, m2z, v.w)));
                            best = fminf(best, t);
                        }
                    }
                    if (xb <= G - 1) {
                        int c0 = rowbase + xb;
                        int p0 = __ldg(&cellstart[c0]), p1 = __ldg(&cellstart[c0 + 1]);
                        for (int p = p0; p < p1; p++) {
                            float4 v = sorted[p];
                            float t = fmaf(v.x, m2x, fmaf(v.y, m2y, fmaf(v.z, m2z, v.w)));
                            best = fminf(best, t);
                        }
                    }
                }
            }
        }
        if (zlo == 0 && ylo == 0 && xlo == 0 &&
            zhi == G - 1 && yhi == G - 1 && xhi == G - 1) break;
    }
    return fmaxf(best + qw, 0.0f);
}

// ---------------- kernel 0: init (both grids) ----------------
__global__ void init_kernel() {
    int i = blockIdx.x * 256 + threadIdx.x;
    if (i < NCELLS)  { g_count[i] = 0;  g_cursor[i] = 0; }
    if (i < NCELLS2) { g_count2[i] = 0; g_cursor2[i] = 0; }
    if (i == 0) {
        g_maxbits = 0u;
        for (int k = 0; k < 3; k++) { g_bbox[k] = 0xFFFFFFFFu;  g_bbox[k + 3] = 0u; }
        for (int k = 0; k < 3; k++) { g_bbox2[k] = 0xFFFFFFFFu; g_bbox2[k + 3] = 0u; }
    }
}

// ---------------- kernel A: prep (bboxes, barycenters) ----------------
__global__ void prep_kernel(const float* __restrict__ ov,
                            const int*   __restrict__ of,
                            const float* __restrict__ sv,
                            const int*   __restrict__ sf) {
    int i = blockIdx.x * 256 + threadIdx.x;

    // bbox of original vertices
    {
        float mnx =  3.0e38f, mxx = -3.0e38f;
        float mny =  3.0e38f, mxy = -3.0e38f;
        float mnz =  3.0e38f, mxz = -3.0e38f;
        if (i < N_OV) {
            mnx = mxx = ov[3 * i];
            mny = mxy = ov[3 * i + 1];
            mnz = mxz = ov[3 * i + 2];
        }
#pragma unroll
        for (int o = 16; o > 0; o >>= 1) {
            mnx = fminf(mnx, __shfl_xor_sync(0xffffffffu, mnx, o));
            mny = fminf(mny, __shfl_xor_sync(0xffffffffu, mny, o));
            mnz = fminf(mnz, __shfl_xor_sync(0xffffffffu, mnz, o));
            mxx = fmaxf(mxx, __shfl_xor_sync(0xffffffffu, mxx, o));
            mxy = fmaxf(mxy, __shfl_xor_sync(0xffffffffu, mxy, o));
            mxz = fmaxf(mxz, __shfl_xor_sync(0xffffffffu, mxz, o));
        }
        if ((threadIdx.x & 31) == 0 && (blockIdx.x * 256 + (threadIdx.x & ~31)) < N_OV) {
            atomicMin(&g_bbox[0], f2o(mnx));
            atomicMin(&g_bbox[1], f2o(mny));
            atomicMin(&g_bbox[2], f2o(mnz));
            atomicMax(&g_bbox[3], f2o(mxx));
            atomicMax(&g_bbox[4], f2o(mxy));
            atomicMax(&g_bbox[5], f2o(mxz));
        }
    }
    // original barycenters + their bbox
    {
        float bx, by, bz;
        float mnx =  3.0e38f, mxx = -3.0e38f;
        float mny =  3.0e38f, mxy = -3.0e38f;
        float mnz =  3.0e38f, mxz = -3.0e38f;
        if (i < N_OF) {
            int f0 = of[3 * i], f1 = of[3 * i + 1], f2 = of[3 * i + 2];
            bx = (ov[3 * f0] + ov[3 * f1] + ov[3 * f2]) / 3.0f;
            by = (ov[3 * f0 + 1] + ov[3 * f1 + 1] + ov[3 * f2 + 1]) / 3.0f;
            bz = (ov[3 * f0 + 2] + ov[3 * f1 + 2] + ov[3 * f2 + 2]) / 3.0f;
            g_obp[i] = make_float4(bx, by, bz, bx * bx + by * by + bz * bz);
            mnx = mxx = bx; mny = mxy = by; mnz = mxz = bz;
        }
#pragma unroll
        for (int o = 16; o > 0; o >>= 1) {
            mnx = fminf(mnx, __shfl_xor_sync(0xffffffffu, mnx, o));
            mny = fminf(mny, __shfl_xor_sync(0xffffffffu, mny, o));
            mnz = fminf(mnz, __shfl_xor_sync(0xffffffffu, mnz, o));
            mxx = fmaxf(mxx, __shfl_xor_sync(0xffffffffu, mxx, o));
            mxy = fmaxf(mxy, __shfl_xor_sync(0xffffffffu, mxy, o));
            mxz = fmaxf(mxz, __shfl_xor_sync(0xffffffffu, mxz, o));
        }
        if ((threadIdx.x & 31) == 0 && (blockIdx.x * 256 + (threadIdx.x & ~31)) < N_OF) {
            atomicMin(&g_bbox2[0], f2o(mnx));
            atomicMin(&g_bbox2[1], f2o(mny));
            atomicMin(&g_bbox2[2], f2o(mnz));
            atomicMax(&g_bbox2[3], f2o(mxx));
            atomicMax(&g_bbox2[4], f2o(mxy));
            atomicMax(&g_bbox2[5], f2o(mxz));
        }
    }
    if (i < N_SF) {
        int f0 = sf[3 * i], f1 = sf[3 * i + 1], f2 = sf[3 * i + 2];
        float bx = (sv[3 * f0] + sv[3 * f1] + sv[3 * f2]) / 3.0f;
        float by = (sv[3 * f0 + 1] + sv[3 * f1 + 1] + sv[3 * f2 + 1]) / 3.0f;
        float bz = (sv[3 * f0 + 2] + sv[3 * f1 + 2] + sv[3 * f2 + 2]) / 3.0f;
        g_sb[i] = make_float4(bx, by, bz, bx * bx + by * by + bz * bz);
    }
}

// ---------------- kernel C: sample generation ----------------
__global__ void gen_samples_kernel(const float* __restrict__ sv,
                                   const int*   __restrict__ sf) {
    int j = blockIdx.x * 256 + threadIdx.x;
    if (j >= N_SAMPLES) return;

    uint32_t rk1_0, rk1_1, rk2_0, rk2_1;
    threefry2x32(0u, 42u, 0u, 0u, rk1_0, rk1_1);
    threefry2x32(0u, 42u, 0u, 1u, rk2_0, rk2_1);

    uint32_t a0, a1, b0, b1;
    threefry2x32(rk1_0, rk1_1, 0u, (uint32_t)j, a0, a1);
    threefry2x32(rk2_0, rk2_1, 0u, (uint32_t)j, b0, b1);

    float u1 = bits_to_uniform(a0 ^ a1);
    float r2 = bits_to_uniform(b0 ^ b1);
    float sq = sqrtf(u1);
    float a = 1.0f - sq;
    float b = sq * (1.0f - r2);
    float c = sq * r2;
    int f = j / NSAMP;
    int i0 = sf[3 * f], i1 = sf[3 * f + 1], i2 = sf[3 * f + 2];
    float x = a * sv[3 * i0]     + b * sv[3 * i1]     + c * sv[3 * i2];
    float y = a * sv[3 * i0 + 1] + b * sv[3 * i1 + 1] + c * sv[3 * i2 + 1];
    float z = a * sv[3 * i0 + 2] + b * sv[3 * i1 + 2] + c * sv[3 * i2 + 2];
    g_samples[j] = make_float4(x, y, z, x * x + y * y + z * z);
}

// ---------------- kernel D1: count (both grids) ----------------
__global__ void count_kernel(const float* __restrict__ ov) {
    int i = blockIdx.x * 256 + threadIdx.x;
    if (i < N_OV) {
        GridGeom g = load_geom(g_bbox, GRID_G);
        int cx = cell_coord(ov[3 * i],     g.x0, g.invh, GRID_G);
        int cy = cell_coord(ov[3 * i + 1], g.y0, g.invh, GRID_G);
        int cz = cell_coord(ov[3 * i + 2], g.z0, g.invh, GRID_G);
        atomicAdd(&g_count[(cz * GRID_G + cy) * GRID_G + cx], 1);
    }
    if (i < N_OF) {
        GridGeom g = load_geom(g_bbox2, GRID_G2);
        float4 b = g_obp[i];
        int cx = cell_coord(b.x, g.x0, g.invh, GRID_G2);
        int cy = cell_coord(b.y, g.y0, g.invh, GRID_G2);
        int cz = cell_coord(b.z, g.z0, g.invh, GRID_G2);
        atomicAdd(&g_count2[(cz * GRID_G2 + cy) * GRID_G2 + cx], 1);
    }
}

// ---------------- kernel D2: block-level scans (both grids) ----------------
__global__ void __launch_bounds__(1024) scan1_kernel() {
    __shared__ int sd[1024];
    int tid = threadIdx.x;
    int b = blockIdx.x;
    if (b < SCAN_BLOCKS) {
        int cell = b * 1024 + tid;
        int cnt = g_count[cell];
        sd[tid] = cnt;
        __syncthreads();
#pragma unroll
        for (int off = 1; off < 1024; off <<= 1) {
            int v = (tid >= off) ? sd[tid - off] : 0;
            __syncthreads();
            sd[tid] += v;
            __syncthreads();
        }
        g_cellstart[cell] = sd[tid] - cnt;
        if (tid == 1023) g_blocksum[b] = sd[1023];
    } else {
        int bb = b - SCAN_BLOCKS;
        int cell = bb * 1024 + tid;
        int cnt = g_count2[cell];
        sd[tid] = cnt;
        __syncthreads();
#pragma unroll
        for (int off = 1; off < 1024; off <<= 1) {
            int v = (tid >= off) ? sd[tid - off] : 0;
            __syncthreads();
            sd[tid] += v;
            __syncthreads();
        }
        g_cellstart2[cell] = sd[tid] - cnt;
        if (tid == 1023) g_blocksum2[bb] = sd[1023];
    }
}

// ---------------- kernel D3: scan of block sums (both grids) ----------------
__global__ void __launch_bounds__(256) scan2_kernel() {
    __shared__ int sd[SCAN_BLOCKS];
    int tid = threadIdx.x;
    int v = g_blocksum[tid];
    sd[tid] = v;
    __syncthreads();
#pragma unroll
    for (int off = 1; off < SCAN_BLOCKS; off <<= 1) {
        int w = (tid >= off) ? sd[tid - off] : 0;
        __syncthreads();
        sd[tid] += w;
        __syncthreads();
    }
    g_blockoff[tid] = sd[tid] - v;
    if (tid == SCAN_BLOCKS - 1) g_cellstart[NCELLS] = sd[tid];
    __syncthreads();
    // second grid: 32 block sums, warp scan by threads 0-31
    if (tid < 32) {
        int v2 = g_blocksum2[tid];
        int s = v2;
#pragma unroll
        for (int off = 1; off < 32; off <<= 1) {
            int w = __shfl_up_sync(0xffffffffu, s, off);
            if ((int)(threadIdx.x & 31) >= off) s += w;
        }
        g_blockoff2[tid] = s - v2;
        if (tid == 31) g_cellstart2[NCELLS2] = s;
    }
}

// ---------------- kernel D4: add block offsets (both grids) ----------------
__global__ void __launch_bounds__(1024) scan3_kernel() {
    int b = blockIdx.x;
    int tid = threadIdx.x;
    if (b < SCAN_BLOCKS) {
        int cell = b * 1024 + tid;
        g_cellstart[cell] += g_blockoff[b];
    } else {
        int cell = (b - SCAN_BLOCKS) * 1024 + tid;
        g_cellstart2[cell] += g_blockoff2[b - SCAN_BLOCKS];
    }
}

// ---------------- kernel D5: scatter (both grids) ----------------
__global__ void scatter_kernel(const float* __restrict__ ov) {
    int i = blockIdx.x * 256 + threadIdx.x;
    if (i < N_OV) {
        GridGeom g = load_geom(g_bbox, GRID_G);
        float x = ov[3 * i], y = ov[3 * i + 1], z = ov[3 * i + 2];
        int cx = cell_coord(x, g.x0, g.invh, GRID_G);
        int cy = cell_coord(y, g.y0, g.invh, GRID_G);
        int cz = cell_coord(z, g.z0, g.invh, GRID_G);
        int c = (cz * GRID_G + cy) * GRID_G + cx;
        int pos = g_cellstart[c] + atomicAdd(&g_cursor[c], 1);
        g_sorted[pos] = make_float4(x, y, z, x * x + y * y + z * z);
    }
    if (i < N_OF) {
        GridGeom g = load_geom(g_bbox2, GRID_G2);
        float4 b = g_obp[i];
        int cx = cell_coord(b.x, g.x0, g.invh, GRID_G2);
        int cy = cell_coord(b.y, g.y0, g.invh, GRID_G2);
        int cz = cell_coord(b.z, g.z0, g.invh, GRID_G2);
        int c = (cz * GRID_G2 + cy) * GRID_G2 + cx;
        int pos = g_cellstart2[c] + atomicAdd(&g_cursor2[c], 1);
        g_sorted2[pos] = b;
    }
}

// ---------------- kernel E1: forward 1-NN via grid2 ----------------
__global__ void __launch_bounds__(256) forward_grid_kernel() {
    int q = blockIdx.x * 256 + threadIdx.x;
    if (q >= N_SF) return;
    GridGeom g = load_geom(g_bbox2, GRID_G2);
    float4 Q = g_sb[q];
    float d2 = shell_nn<GRID_G2>(Q.x, Q.y, Q.z, Q.w, g, g_cellstart2, g_sorted2);
    g_minfwd[q] = __float_as_uint(d2);
}

// ---------------- kernel E2: reverse 1-NN via grid + fused reductions -------
__global__ void __launch_bounds__(256) reverse_grid_kernel(const float* __restrict__ fp) {
    int j = blockIdx.x * 256 + threadIdx.x;

    float d = 0.0f;
    double contrib = 0.0;
    if (j < N_SAMPLES) {
        GridGeom g = load_geom(g_bbox, GRID_G);
        float4 s = g_samples[j];
        float d2 = shell_nn<GRID_G>(s.x, s.y, s.z, s.w, g, g_cellstart, g_sorted);
        d = sqrtf(d2);
        contrib = (double)(fp[j / NSAMP] * d);
    }

    __shared__ double rsum[256];
    __shared__ float rmax[256];
    int tid = threadIdx.x;
    rsum[tid] = contrib;
    rmax[tid] = d;
    __syncthreads();
#pragma unroll
    for (int o = 128; o > 0; o >>= 1) {
        if (tid < o) {
            rsum[tid] += rsum[tid + o];
            rmax[tid] = fmaxf(rmax[tid], rmax[tid + o]);
        }
        __syncthreads();
    }
    if (tid == 0) {
        g_part[blockIdx.x] = rsum[0];
        atomicMax(&g_maxbits, __float_as_uint(rmax[0]));
    }
}

// ---------------- kernel F: final ----------------
__global__ void __launch_bounds__(512) final_kernel(const float* __restrict__ fp,
                                                    float* __restrict__ out) {
    __shared__ double red[512];
    int tid = threadIdx.x;

    double fwd = 0.0, pen = 0.0, rev = 0.0;
    for (int i = tid; i < N_SF; i += 512) {
        float p = fp[i];
        float d2 = __uint_as_float(g_minfwd[i]);
        fwd += (double)(p * sqrtf(d2));
        pen += (double)(1.0f - p);
    }
    for (int b = tid; b < REV_BLOCKS; b += 512) rev += g_part[b];

    double totF, totP, totR;
    red[tid] = fwd; __syncthreads();
    for (int o = 256; o > 0; o >>= 1) { if (tid < o) red[tid] += red[tid + o]; __syncthreads(); }
    totF = red[0]; __syncthreads();
    red[tid] = pen; __syncthreads();
    for (int o = 256; o > 0; o >>= 1) { if (tid < o) red[tid] += red[tid + o]; __syncthreads(); }
    totP = red[0]; __syncthreads();
    red[tid] = rev; __syncthreads();
    for (int o = 256; o > 0; o >>= 1) { if (tid < o) red[tid] += red[tid + o]; __syncthreads(); }
    totR = red[0];

    if (tid == 0) {
        double maxd = (double)__uint_as_float(g_maxbits);
        double result = totF + 1e-4 * totP + totR / (maxd + 1e-8) * 0.1;
        out[0] = (float)result;
    }
}

// ---------------- launch ----------------
extern "C" void kernel_launch(void* const* d_in, const int* in_sizes, int n_in,
                              void* d_out, int out_size) {
    const float* ov = (const float*)d_in[0];
    const int*   of = (const int*)  d_in[1];
    const float* sv = (const float*)d_in[2];
    const int*   sf = (const int*)  d_in[3];
    const float* fp = (const float*)d_in[4];
    float* out = (float*)d_out;

    init_kernel<<<(NCELLS + 255) / 256, 256>>>();
    prep_kernel<<<(N_OF + 255) / 256, 256>>>(ov, of, sv, sf);
    gen_samples_kernel<<<(N_SAMPLES + 255) / 256, 256>>>(sv, sf);

    // grid builds (both grids fused per phase)
    count_kernel<<<(N_OF + 255) / 256, 256>>>(ov);
    scan1_kernel<<<SCAN_BLOCKS + SCAN_BLOCKS2, 1024>>>();
    scan2_kernel<<<1, 256>>>();
    scan3_kernel<<<SCAN_BLOCKS + SCAN_BLOCKS2, 1024>>>();
    scatter_kernel<<<(N_OF + 255) / 256, 256>>>(ov);

    forward_grid_kernel<<<FWD_BLOCKS, 256>>>();
    reverse_grid_kernel<<<REV_BLOCKS, 256>>>(fp);
    final_kernel<<<1, 512>>>(fp, out);
}

// round 8
// speedup vs baseline: 1.2520x; 1.2520x over previous
#include <cuda_runtime.h>
#include <cuda_bf16.h>
#include <stdint.h>

// ---------------- problem constants (static shapes) ----------------
#define N_OV 20000
#define N_OF 30000
#define N_SV 4000
#define N_SF 5000
#define NSAMP 50
#define N_SAMPLES 250000
// vertex grid (reverse term)
#define GRID_G 64
#define NCELLS (GRID_G * GRID_G * GRID_G)       // 262144
#define SCAN_BLOCKS 256
// barycenter grid (forward term)
#define GRID_G2 32
#define NCELLS2 (GRID_G2 * GRID_G2 * GRID_G2)   // 32768
#define SCAN_BLOCKS2 32
#define REV_BLOCKS 977                           // ceil(250000/256)
#define FWD_WARP_BLOCKS 625                      // 5000 warps, 8 per block

// ---------------- device scratch (static, no runtime alloc) ----------------
__device__ float4    g_obp[N_OF];
__device__ float4    g_sb[N_SF];
__device__ unsigned  g_minfwd[N_SF];
__device__ float4    g_samples[N_SAMPLES];
__device__ unsigned  g_maxbits;
__device__ double    g_part[REV_BLOCKS];
// grid V (vertices)
__device__ unsigned  g_bbox[6];
__device__ int       g_count[NCELLS];
__device__ int       g_cursor[NCELLS];
__device__ int       g_cellstart[NCELLS + 1];
__device__ int       g_blocksum[SCAN_BLOCKS];
__device__ int       g_blockoff[SCAN_BLOCKS];
__device__ float4    g_sorted[N_OV];
// grid B (original barycenters)
__device__ unsigned  g_bbox2[6];
__device__ int       g_count2[NCELLS2];
__device__ int       g_cursor2[NCELLS2];
__device__ int       g_cellstart2[NCELLS2 + 1];
__device__ int       g_blocksum2[SCAN_BLOCKS2];
__device__ int       g_blockoff2[SCAN_BLOCKS2];
__device__ float4    g_sorted2[N_OF];

// ---------------- ordered-float helpers ----------------
__device__ __forceinline__ unsigned f2o(float f) {
    unsigned u = __float_as_uint(f);
    return (u & 0x80000000u) ? ~u : (u | 0x80000000u);
}
__device__ __forceinline__ float o2f(unsigned u) {
    u = (u & 0x80000000u) ? (u & 0x7fffffffu) : ~u;
    return __uint_as_float(u);
}

// ---------------- threefry2x32 (JAX partitionable, 20 rounds) ----------------
__host__ __device__ constexpr uint32_t rotl32(uint32_t x, int r) {
    return (x << r) | (x >> (32 - r));
}
struct U2 { uint32_t a, b; };
__host__ __device__ constexpr U2 threefry2x32(uint32_t k0, uint32_t k1,
                                              uint32_t x0, uint32_t x1) {
    uint32_t ks0 = k0, ks1 = k1, ks2 = k0 ^ k1 ^ 0x1BD11BDAu;
    x0 += ks0; x1 += ks1;
    x0 += x1; x1 = rotl32(x1, 13); x1 ^= x0;
    x0 += x1; x1 = rotl32(x1, 15); x1 ^= x0;
    x0 += x1; x1 = rotl32(x1, 26); x1 ^= x0;
    x0 += x1; x1 = rotl32(x1,  6); x1 ^= x0;
    x0 += ks1; x1 += ks2 + 1u;
    x0 += x1; x1 = rotl32(x1, 17); x1 ^= x0;
    x0 += x1; x1 = rotl32(x1, 29); x1 ^= x0;
    x0 += x1; x1 = rotl32(x1, 16); x1 ^= x0;
    x0 += x1; x1 = rotl32(x1, 24); x1 ^= x0;
    x0 += ks2; x1 += ks0 + 2u;
    x0 += x1; x1 = rotl32(x1, 13); x1 ^= x0;
    x0 += x1; x1 = rotl32(x1, 15); x1 ^= x0;
    x0 += x1; x1 = rotl32(x1, 26); x1 ^= x0;
    x0 += x1; x1 = rotl32(x1,  6); x1 ^= x0;
    x0 += ks0; x1 += ks1 + 3u;
    x0 += x1; x1 = rotl32(x1, 17); x1 ^= x0;
    x0 += x1; x1 = rotl32(x1, 29); x1 ^= x0;
    x0 += x1; x1 = rotl32(x1, 16); x1 ^= x0;
    x0 += x1; x1 = rotl32(x1, 24); x1 ^= x0;
    x0 += ks1; x1 += ks2 + 4u;
    x0 += x1; x1 = rotl32(x1, 13); x1 ^= x0;
    x0 += x1; x1 = rotl32(x1, 15); x1 ^= x0;
    x0 += x1; x1 = rotl32(x1, 26); x1 ^= x0;
    x0 += x1; x1 = rotl32(x1,  6); x1 ^= x0;
    x0 += ks2; x1 += ks0 + 5u;
    return {x0, x1};
}
// compile-time fold_in subkeys from key(42) = (0,42)
constexpr U2 RK1 = threefry2x32(0u, 42u, 0u, 0u);
constexpr U2 RK2 = threefry2x32(0u, 42u, 0u, 1u);

__device__ __forceinline__ float bits_to_uniform(uint32_t bits) {
    return __uint_as_float((bits >> 9) | 0x3f800000u) - 1.0f;
}

// ---------------- grid geometry ----------------
struct GridGeom { float x0, y0, z0, invh, h; };
__device__ __forceinline__ GridGeom load_geom(const unsigned* bbox, int G) {
    GridGeom g;
    g.x0 = o2f(bbox[0]); g.y0 = o2f(bbox[1]); g.z0 = o2f(bbox[2]);
    float ex = o2f(bbox[3]) - g.x0;
    float ey = o2f(bbox[4]) - g.y0;
    float ez = o2f(bbox[5]) - g.z0;
    float e = fmaxf(fmaxf(ex, ey), fmaxf(ez, 1e-20f));
    g.h = e / (float)G;
    g.invh = (float)G / e;
    return g;
}
__device__ __forceinline__ int cell_coord(float v, float v0, float invh, int G) {
    int c = (int)((v - v0) * invh);
    return min(max(c, 0), G - 1);
}

// ---------------- exact expanding-shell 1-NN, one thread per query ---------
template <int G>
__device__ __forceinline__ float shell_nn(float qx, float qy, float qz, float qw,
                                          const GridGeom g,
                                          const int* __restrict__ cellstart,
                                          const float4* __restrict__ sorted) {
    float m2x = -2.0f * qx, m2y = -2.0f * qy, m2z = -2.0f * qz;
    int cx = cell_coord(qx, g.x0, g.invh, G);
    int cy = cell_coord(qy, g.y0, g.invh, G);
    int cz = cell_coord(qz, g.z0, g.invh, G);

    float best = 3.0e38f;
    for (int R = 0; R <= G; R++) {
        if (R > 0) {
            float lb = (float)(R - 1) * g.h;
            if (best + qw <= lb * lb) break;
        }
        int zlo = max(cz - R, 0), zhi = min(cz + R, G - 1);
        int ylo = max(cy - R, 0), yhi = min(cy + R, G - 1);
        int xlo = max(cx - R, 0), xhi = min(cx + R, G - 1);
        for (int z = zlo; z <= zhi; z++) {
            bool ze = (z == cz - R) || (z == cz + R);
            for (int y = ylo; y <= yhi; y++) {
                bool edge = ze || (y == cy - R) || (y == cy + R);
                int rowbase = (z * G + y) * G;
                if (edge) {
                    int p0 = __ldg(&cellstart[rowbase + xlo]);
                    int p1 = __ldg(&cellstart[rowbase + xhi + 1]);
                    for (int p = p0; p < p1; p++) {
                        float4 v = sorted[p];
                        float t = fmaf(v.x, m2x, fmaf(v.y, m2y, fmaf(v.z, m2z, v.w)));
                        best = fminf(best, t);
                    }
                } else {
                    int xa = cx - R, xb = cx + R;
                    if (xa >= 0) {
                        int c0 = rowbase + xa;
                        int p0 = __ldg(&cellstart[c0]), p1 = __ldg(&cellstart[c0 + 1]);
                        for (int p = p0; p < p1; p++) {
                            float4 v = sorted[p];
                            float t = fmaf(v.x, m2x, fmaf(v.y, m2y, fmaf(v.z, m2z, v.w)));
                            best = fminf(best, t);
                        }
                    }
                    if (xb <= G - 1) {
                        int c0 = rowbase + xb;
                        int p0 = __ldg(&cellstart[c0]), p1 = __ldg(&cellstart[c0 + 1]);
                        for (int p = p0; p < p1; p++) {
                            float4 v = sorted[p];
                            float t = fmaf(v.x, m2x, fmaf(v.y, m2y, fmaf(v.z, m2z, v.w)));
                            best = fminf(best, t);
                        }
                    }
                }
            }
        }
        if (zlo == 0 && ylo == 0 && xlo == 0 &&
            zhi == G - 1 && yhi == G - 1 && xhi == G - 1) break;
    }
    return fmaxf(best + qw, 0.0f);
}

// ---------------- kernel A: fused init + prep ----------------
__global__ void init_prep_kernel(const float* __restrict__ ov,
                                 const int*   __restrict__ of,
                                 const float* __restrict__ sv,
                                 const int*   __restrict__ sf) {
    int i = blockIdx.x * 256 + threadIdx.x;
    if (i < NCELLS)  { g_count[i] = 0;  g_cursor[i] = 0; }
    if (i < NCELLS2) { g_count2[i] = 0; g_cursor2[i] = 0; }
    if (i == 0) {
        g_maxbits = 0u;
        for (int k = 0; k < 3; k++) { g_bbox[k] = 0xFFFFFFFFu;  g_bbox[k + 3] = 0u; }
        for (int k = 0; k < 3; k++) { g_bbox2[k] = 0xFFFFFFFFu; g_bbox2[k + 3] = 0u; }
    }

    // bbox of original vertices
    {
        float mnx =  3.0e38f, mxx = -3.0e38f;
        float mny =  3.0e38f, mxy = -3.0e38f;
        float mnz =  3.0e38f, mxz = -3.0e38f;
        if (i < N_OV) {
            mnx = mxx = ov[3 * i];
            mny = mxy = ov[3 * i + 1];
            mnz = mxz = ov[3 * i + 2];
        }
#pragma unroll
        for (int o = 16; o > 0; o >>= 1) {
            mnx = fminf(mnx, __shfl_xor_sync(0xffffffffu, mnx, o));
            mny = fminf(mny, __shfl_xor_sync(0xffffffffu, mny, o));
            mnz = fminf(mnz, __shfl_xor_sync(0xffffffffu, mnz, o));
            mxx = fmaxf(mxx, __shfl_xor_sync(0xffffffffu, mxx, o));
            mxy = fmaxf(mxy, __shfl_xor_sync(0xffffffffu, mxy, o));
            mxz = fmaxf(mxz, __shfl_xor_sync(0xffffffffu, mxz, o));
        }
        if ((threadIdx.x & 31) == 0 && (blockIdx.x * 256 + (threadIdx.x & ~31)) < N_OV) {
            atomicMin(&g_bbox[0], f2o(mnx));
            atomicMin(&g_bbox[1], f2o(mny));
            atomicMin(&g_bbox[2], f2o(mnz));
            atomicMax(&g_bbox[3], f2o(mxx));
            atomicMax(&g_bbox[4], f2o(mxy));
            atomicMax(&g_bbox[5], f2o(mxz));
        }
    }
    // original barycenters + their bbox
    {
        float bx, by, bz;
        float mnx =  3.0e38f, mxx = -3.0e38f;
        float mny =  3.0e38f, mxy = -3.0e38f;
        float mnz =  3.0e38f, mxz = -3.0e38f;
        if (i < N_OF) {
            int f0 = of[3 * i], f1 = of[3 * i + 1], f2 = of[3 * i + 2];
            bx = (ov[3 * f0] + ov[3 * f1] + ov[3 * f2]) / 3.0f;
            by = (ov[3 * f0 + 1] + ov[3 * f1 + 1] + ov[3 * f2 + 1]) / 3.0f;
            bz = (ov[3 * f0 + 2] + ov[3 * f1 + 2] + ov[3 * f2 + 2]) / 3.0f;
            g_obp[i] = make_float4(bx, by, bz, bx * bx + by * by + bz * bz);
            mnx = mxx = bx; mny = mxy = by; mnz = mxz = bz;
        }
#pragma unroll
        for (int o = 16; o > 0; o >>= 1) {
            mnx = fminf(mnx, __shfl_xor_sync(0xffffffffu, mnx, o));
            mny = fminf(mny, __shfl_xor_sync(0xffffffffu, mny, o));
            mnz = fminf(mnz, __shfl_xor_sync(0xffffffffu, mnz, o));
            mxx = fmaxf(mxx, __shfl_xor_sync(0xffffffffu, mxx, o));
            mxy = fmaxf(mxy, __shfl_xor_sync(0xffffffffu, mxy, o));
            mxz = fmaxf(mxz, __shfl_xor_sync(0xffffffffu, mxz, o));
        }
        if ((threadIdx.x & 31) == 0 && (blockIdx.x * 256 + (threadIdx.x & ~31)) < N_OF) {
            atomicMin(&g_bbox2[0], f2o(mnx));
            atomicMin(&g_bbox2[1], f2o(mny));
            atomicMin(&g_bbox2[2], f2o(mnz));
            atomicMax(&g_bbox2[3], f2o(mxx));
            atomicMax(&g_bbox2[4], f2o(mxy));
            atomicMax(&g_bbox2[5], f2o(mxz));
        }
    }
    if (i < N_SF) {
        int f0 = sf[3 * i], f1 = sf[3 * i + 1], f2 = sf[3 * i + 2];
        float bx = (sv[3 * f0] + sv[3 * f1] + sv[3 * f2]) / 3.0f;
        float by = (sv[3 * f0 + 1] + sv[3 * f1 + 1] + sv[3 * f2 + 1]) / 3.0f;
        float bz = (sv[3 * f0 + 2] + sv[3 * f1 + 2] + sv[3 * f2 + 2]) / 3.0f;
        g_sb[i] = make_float4(bx, by, bz, bx * bx + by * by + bz * bz);
    }
}

// ---------------- kernel C: sample generation ----------------
__global__ void gen_samples_kernel(const float* __restrict__ sv,
                                   const int*   __restrict__ sf) {
    int j = blockIdx.x * 256 + threadIdx.x;
    if (j >= N_SAMPLES) return;

    U2 ua = threefry2x32(RK1.a, RK1.b, 0u, (uint32_t)j);
    U2 ub = threefry2x32(RK2.a, RK2.b, 0u, (uint32_t)j);

    float u1 = bits_to_uniform(ua.a ^ ua.b);
    float r2 = bits_to_uniform(ub.a ^ ub.b);
    float sq = sqrtf(u1);
    float a = 1.0f - sq;
    float b = sq * (1.0f - r2);
    float c = sq * r2;
    int f = j / NSAMP;
    int i0 = sf[3 * f], i1 = sf[3 * f + 1], i2 = sf[3 * f + 2];
    float x = a * sv[3 * i0]     + b * sv[3 * i1]     + c * sv[3 * i2];
    float y = a * sv[3 * i0 + 1] + b * sv[3 * i1 + 1] + c * sv[3 * i2 + 1];
    float z = a * sv[3 * i0 + 2] + b * sv[3 * i1 + 2] + c * sv[3 * i2 + 2];
    g_samples[j] = make_float4(x, y, z, x * x + y * y + z * z);
}

// ---------------- kernel D1: count (both grids) ----------------
__global__ void count_kernel(const float* __restrict__ ov) {
    int i = blockIdx.x * 256 + threadIdx.x;
    if (i < N_OV) {
        GridGeom g = load_geom(g_bbox, GRID_G);
        int cx = cell_coord(ov[3 * i],     g.x0, g.invh, GRID_G);
        int cy = cell_coord(ov[3 * i + 1], g.y0, g.invh, GRID_G);
        int cz = cell_coord(ov[3 * i + 2], g.z0, g.invh, GRID_G);
        atomicAdd(&g_count[(cz * GRID_G + cy) * GRID_G + cx], 1);
    }
    if (i < N_OF) {
        GridGeom g = load_geom(g_bbox2, GRID_G2);
        float4 b = g_obp[i];
        int cx = cell_coord(b.x, g.x0, g.invh, GRID_G2);
        int cy = cell_coord(b.y, g.y0, g.invh, GRID_G2);
        int cz = cell_coord(b.z, g.z0, g.invh, GRID_G2);
        atomicAdd(&g_count2[(cz * GRID_G2 + cy) * GRID_G2 + cx], 1);
    }
}

// ---------------- kernel D2: block-level scans (both grids) ----------------
__global__ void __launch_bounds__(1024) scan1_kernel() {
    __shared__ int sd[1024];
    int tid = threadIdx.x;
    int b = blockIdx.x;
    if (b < SCAN_BLOCKS) {
        int cell = b * 1024 + tid;
        int cnt = g_count[cell];
        sd[tid] = cnt;
        __syncthreads();
#pragma unroll
        for (int off = 1; off < 1024; off <<= 1) {
            int v = (tid >= off) ? sd[tid - off] : 0;
            __syncthreads();
            sd[tid] += v;
            __syncthreads();
        }
        g_cellstart[cell] = sd[tid] - cnt;
        if (tid == 1023) g_blocksum[b] = sd[1023];
    } else {
        int bb = b - SCAN_BLOCKS;
        int cell = bb * 1024 + tid;
        int cnt = g_count2[cell];
        sd[tid] = cnt;
        __syncthreads();
#pragma unroll
        for (int off = 1; off < 1024; off <<= 1) {
            int v = (tid >= off) ? sd[tid - off] : 0;
            __syncthreads();
            sd[tid] += v;
            __syncthreads();
        }
        g_cellstart2[cell] = sd[tid] - cnt;
        if (tid == 1023) g_blocksum2[bb] = sd[1023];
    }
}

// ---------------- kernel D3: scan of block sums (both grids) ----------------
__global__ void __launch_bounds__(256) scan2_kernel() {
    __shared__ int sd[SCAN_BLOCKS];
    int tid = threadIdx.x;
    int v = g_blocksum[tid];
    sd[tid] = v;
    __syncthreads();
#pragma unroll
    for (int off = 1; off < SCAN_BLOCKS; off <<= 1) {
        int w = (tid >= off) ? sd[tid - off] : 0;
        __syncthreads();
        sd[tid] += w;
        __syncthreads();
    }
    g_blockoff[tid] = sd[tid] - v;
    if (tid == SCAN_BLOCKS - 1) g_cellstart[NCELLS] = sd[tid];
    __syncthreads();
    if (tid < 32) {
        int v2 = g_blocksum2[tid];
        int s = v2;
#pragma unroll
        for (int off = 1; off < 32; off <<= 1) {
            int w = __shfl_up_sync(0xffffffffu, s, off);
            if ((int)(threadIdx.x & 31) >= off) s += w;
        }
        g_blockoff2[tid] = s - v2;
        if (tid == 31) g_cellstart2[NCELLS2] = s;
    }
}

// ---------------- kernel D4: add block offsets (both grids) ----------------
__global__ void __launch_bounds__(1024) scan3_kernel() {
    int b = blockIdx.x;
    int tid = threadIdx.x;
    if (b < SCAN_BLOCKS) {
        int cell = b * 1024 + tid;
        g_cellstart[cell] += g_blockoff[b];
    } else {
        int cell = (b - SCAN_BLOCKS) * 1024 + tid;
        g_cellstart2[cell] += g_blockoff2[b - SCAN_BLOCKS];
    }
}

// ---------------- kernel D5: scatter (both grids) ----------------
__global__ void scatter_kernel(const float* __restrict__ ov) {
    int i = blockIdx.x * 256 + threadIdx.x;
    if (i < N_OV) {
        GridGeom g = load_geom(g_bbox, GRID_G);
        float x = ov[3 * i], y = ov[3 * i + 1], z = ov[3 * i + 2];
        int cx = cell_coord(x, g.x0, g.invh, GRID_G);
        int cy = cell_coord(y, g.y0, g.invh, GRID_G);
        int cz = cell_coord(z, g.z0, g.invh, GRID_G);
        int c = (cz * GRID_G + cy) * GRID_G + cx;
        int pos = g_cellstart[c] + atomicAdd(&g_cursor[c], 1);
        g_sorted[pos] = make_float4(x, y, z, x * x + y * y + z * z);
    }
    if (i < N_OF) {
        GridGeom g = load_geom(g_bbox2, GRID_G2);
        float4 b = g_obp[i];
        int cx = cell_coord(b.x, g.x0, g.invh, GRID_G2);
        int cy = cell_coord(b.y, g.y0, g.invh, GRID_G2);
        int cz = cell_coord(b.z, g.z0, g.invh, GRID_G2);
        int c = (cz * GRID_G2 + cy) * GRID_G2 + cx;
        int pos = g_cellstart2[c] + atomicAdd(&g_cursor2[c], 1);
        g_sorted2[pos] = b;
    }
}

// ---------------- kernel E1: forward 1-NN, one WARP per query --------------
__global__ void __launch_bounds__(256) forward_warp_kernel() {
    int warp = (blockIdx.x * 256 + threadIdx.x) >> 5;
    int lane = threadIdx.x & 31;
    if (warp >= N_SF) return;

    GridGeom g = load_geom(g_bbox2, GRID_G2);
    float4 Q = g_sb[warp];
    float m2x = -2.0f * Q.x, m2y = -2.0f * Q.y, m2z = -2.0f * Q.z;
    int cx = cell_coord(Q.x, g.x0, g.invh, GRID_G2);
    int cy = cell_coord(Q.y, g.y0, g.invh, GRID_G2);
    int cz = cell_coord(Q.z, g.z0, g.invh, GRID_G2);
    const int G = GRID_G2;

    float best = 3.0e38f;   // per-lane best t
    for (int R = 0; R <= G; R++) {
        // warp-uniform break test on reduced min
        float bmin = best;
#pragma unroll
        for (int o = 16; o > 0; o >>= 1)
            bmin = fminf(bmin, __shfl_xor_sync(0xffffffffu, bmin, o));
        if (R > 0) {
            float lb = (float)(R - 1) * g.h;
            if (bmin + Q.w <= lb * lb) break;
        }
        int zlo = max(cz - R, 0), zhi = min(cz + R, G - 1);
        int ylo = max(cy - R, 0), yhi = min(cy + R, G - 1);
        int xlo = max(cx - R, 0), xhi = min(cx + R, G - 1);
        for (int z = zlo; z <= zhi; z++) {
            bool ze = (z == cz - R) || (z == cz + R);
            for (int y = ylo; y <= yhi; y++) {
                bool edge = ze || (y == cy - R) || (y == cy + R);
                int rowbase = (z * G + y) * G;
                if (edge) {
                    int p0 = __ldg(&g_cellstart2[rowbase + xlo]);
                    int p1 = __ldg(&g_cellstart2[rowbase + xhi + 1]);
                    for (int p = p0 + lane; p < p1; p += 32) {
                        float4 v = g_sorted2[p];
                        float t = fmaf(v.x, m2x, fmaf(v.y, m2y, fmaf(v.z, m2z, v.w)));
                        best = fminf(best, t);
                    }
                } else {
                    int xa = cx - R, xb = cx + R;
                    if (xa >= 0) {
                        int c0 = rowbase + xa;
                        int p0 = __ldg(&g_cellstart2[c0]), p1 = __ldg(&g_cellstart2[c0 + 1]);
                        for (int p = p0 + lane; p < p1; p += 32) {
                            float4 v = g_sorted2[p];
                            float t = fmaf(v.x, m2x, fmaf(v.y, m2y, fmaf(v.z, m2z, v.w)));
                            best = fminf(best, t);
                        }
                    }
                    if (xb <= G - 1) {
                        int c0 = rowbase + xb;
                        int p0 = __ldg(&g_cellstart2[c0]), p1 = __ldg(&g_cellstart2[c0 + 1]);
                        for (int p = p0 + lane; p < p1; p += 32) {
                            float4 v = g_sorted2[p];
                            float t = fmaf(v.x, m2x, fmaf(v.y, m2y, fmaf(v.z, m2z, v.w)));
                            best = fminf(best, t);
                        }
                    }
                }
            }
        }
        if (zlo == 0 && ylo == 0 && xlo == 0 &&
            zhi == G - 1 && yhi == G - 1 && xhi == G - 1) break;
    }
    float bmin = best;
#pragma unroll
    for (int o = 16; o > 0; o >>= 1)
        bmin = fminf(bmin, __shfl_xor_sync(0xffffffffu, bmin, o));
    if (lane == 0)
        g_minfwd[warp] = __float_as_uint(fmaxf(bmin + Q.w, 0.0f));
}

// ---------------- kernel E2: reverse 1-NN via grid + fused reductions -------
__global__ void __launch_bounds__(256) reverse_grid_kernel(const float* __restrict__ fp) {
    int j = blockIdx.x * 256 + threadIdx.x;

    float d = 0.0f;
    double contrib = 0.0;
    if (j < N_SAMPLES) {
        GridGeom g = load_geom(g_bbox, GRID_G);
        float4 s = g_samples[j];
        float d2 = shell_nn<GRID_G>(s.x, s.y, s.z, s.w, g, g_cellstart, g_sorted);
        d = sqrtf(d2);
        contrib = (double)(fp[j / NSAMP] * d);
    }

    __shared__ double rsum[256];
    __shared__ float rmax[256];
    int tid = threadIdx.x;
    rsum[tid] = contrib;
    rmax[tid] = d;
    __syncthreads();
#pragma unroll
    for (int o = 128; o > 0; o >>= 1) {
        if (tid < o) {
            rsum[tid] += rsum[tid + o];
            rmax[tid] = fmaxf(rmax[tid], rmax[tid + o]);
        }
        __syncthreads();
    }
    if (tid == 0) {
        g_part[blockIdx.x] = rsum[0];
        atomicMax(&g_maxbits, __float_as_uint(rmax[0]));
    }
}

// ---------------- kernel F: final ----------------
__global__ void __launch_bounds__(512) final_kernel(const float* __restrict__ fp,
                                                    float* __restrict__ out) {
    __shared__ double red[512];
    int tid = threadIdx.x;

    double fwd = 0.0, pen = 0.0, rev = 0.0;
    for (int i = tid; i < N_SF; i += 512) {
        float p = fp[i];
        float d2 = __uint_as_float(g_minfwd[i]);
        fwd += (double)(p * sqrtf(d2));
        pen += (double)(1.0f - p);
    }
    for (int b = tid; b < REV_BLOCKS; b += 512) rev += g_part[b];

    double totF, totP, totR;
    red[tid] = fwd; __syncthreads();
    for (int o = 256; o > 0; o >>= 1) { if (tid < o) red[tid] += red[tid + o]; __syncthreads(); }
    totF = red[0]; __syncthreads();
    red[tid] = pen; __syncthreads();
    for (int o = 256; o > 0; o >>= 1) { if (tid < o) red[tid] += red[tid + o]; __syncthreads(); }
    totP = red[0]; __syncthreads();
    red[tid] = rev; __syncthreads();
    for (int o = 256; o > 0; o >>= 1) { if (tid < o) red[tid] += red[tid + o]; __syncthreads(); }
    totR = red[0];

    if (tid == 0) {
        double maxd = (double)__uint_as_float(g_maxbits);
        double result = totF + 1e-4 * totP + totR / (maxd + 1e-8) * 0.1;
        out[0] = (float)result;
    }
}

// ---------------- launch ----------------
extern "C" void kernel_launch(void* const* d_in, const int* in_sizes, int n_in,
                              void* d_out, int out_size) {
    const float* ov = (const float*)d_in[0];
    const int*   of = (const int*)  d_in[1];
    const float* sv = (const float*)d_in[2];
    const int*   sf = (const int*)  d_in[3];
    const float* fp = (const float*)d_in[4];
    float* out = (float*)d_out;

    init_prep_kernel<<<(NCELLS + 255) / 256, 256>>>(ov, of, sv, sf);
    gen_samples_kernel<<<(N_SAMPLES + 255) / 256, 256>>>(sv, sf);

    count_kernel<<<(N_OF + 255) / 256, 256>>>(ov);
    scan1_kernel<<<SCAN_BLOCKS + SCAN_BLOCKS2, 1024>>>();
    scan2_kernel<<<1, 256>>>();
    scan3_kernel<<<SCAN_BLOCKS + SCAN_BLOCKS2, 1024>>>();
    scatter_kernel<<<(N_OF + 255) / 256, 256>>>(ov);

    forward_warp_kernel<<<FWD_WARP_BLOCKS, 256>>>();
    reverse_grid_kernel<<<REV_BLOCKS, 256>>>(fp);
    final_kernel<<<1, 512>>>(fp, out);
}

// round 9
// speedup vs baseline: 1.4239x; 1.1374x over previous
#include <cuda_runtime.h>
#include <cuda_bf16.h>
#include <stdint.h>

// ---------------- problem constants (static shapes) ----------------
#define N_OV 20000
#define N_OF 30000
#define N_SV 4000
#define N_SF 5000
#define NSAMP 50
#define N_SAMPLES 250000
// vertex grid (reverse term) — also used to sort samples
#define GRID_G 64
#define NCELLS (GRID_G * GRID_G * GRID_G)       // 262144
#define SCAN_BLOCKS 256
// barycenter grid (forward term)
#define GRID_G2 32
#define NCELLS2 (GRID_G2 * GRID_G2 * GRID_G2)   // 32768
#define SCAN_BLOCKS2 32
#define REV_BLOCKS 977                           // ceil(250000/256)
#define FWD_WARP_BLOCKS 625                      // 5000 warps

// ---------------- device scratch (static, no runtime alloc) ----------------
__device__ float4    g_obp[N_OF];
__device__ float4    g_sb[N_SF];
__device__ unsigned  g_minfwd[N_SF];
__device__ float4    g_samples[N_SAMPLES];      // unsorted
__device__ float4    g_ssorted[N_SAMPLES];      // cell-sorted samples
__device__ float     g_sfp[N_SAMPLES];          // fp value aligned to sorted order
__device__ unsigned  g_maxbits;
__device__ double    g_part[REV_BLOCKS];
// grid V (vertices)
__device__ unsigned  g_bbox[6];
__device__ int       g_count[NCELLS];
__device__ int       g_cursor[NCELLS];
__device__ int       g_cellstart[NCELLS + 1];
__device__ int       g_blocksum[SCAN_BLOCKS];
__device__ int       g_blockoff[SCAN_BLOCKS];
__device__ float4    g_sorted[N_OV];
// grid B (original barycenters)
__device__ unsigned  g_bbox2[6];
__device__ int       g_count2[NCELLS2];
__device__ int       g_cursor2[NCELLS2];
__device__ int       g_cellstart2[NCELLS2 + 1];
__device__ int       g_blocksum2[SCAN_BLOCKS2];
__device__ int       g_blockoff2[SCAN_BLOCKS2];
__device__ float4    g_sorted2[N_OF];
// grid S (samples, same geometry as grid V)
__device__ int       g_count3[NCELLS];
__device__ int       g_cursor3[NCELLS];
__device__ int       g_cellstart3[NCELLS + 1];
__device__ int       g_blocksum3[SCAN_BLOCKS];
__device__ int       g_blockoff3[SCAN_BLOCKS];

// ---------------- ordered-float helpers ----------------
__device__ __forceinline__ unsigned f2o(float f) {
    unsigned u = __float_as_uint(f);
    return (u & 0x80000000u) ? ~u : (u | 0x80000000u);
}
__device__ __forceinline__ float o2f(unsigned u) {
    u = (u & 0x80000000u) ? (u & 0x7fffffffu) : ~u;
    return __uint_as_float(u);
}

// ---------------- threefry2x32 (JAX partitionable, 20 rounds) ----------------
__host__ __device__ constexpr uint32_t rotl32(uint32_t x, int r) {
    return (x << r) | (x >> (32 - r));
}
struct U2 { uint32_t a, b; };
__host__ __device__ constexpr U2 threefry2x32(uint32_t k0, uint32_t k1,
                                              uint32_t x0, uint32_t x1) {
    uint32_t ks0 = k0, ks1 = k1, ks2 = k0 ^ k1 ^ 0x1BD11BDAu;
    x0 += ks0; x1 += ks1;
    x0 += x1; x1 = rotl32(x1, 13); x1 ^= x0;
    x0 += x1; x1 = rotl32(x1, 15); x1 ^= x0;
    x0 += x1; x1 = rotl32(x1, 26); x1 ^= x0;
    x0 += x1; x1 = rotl32(x1,  6); x1 ^= x0;
    x0 += ks1; x1 += ks2 + 1u;
    x0 += x1; x1 = rotl32(x1, 17); x1 ^= x0;
    x0 += x1; x1 = rotl32(x1, 29); x1 ^= x0;
    x0 += x1; x1 = rotl32(x1, 16); x1 ^= x0;
    x0 += x1; x1 = rotl32(x1, 24); x1 ^= x0;
    x0 += ks2; x1 += ks0 + 2u;
    x0 += x1; x1 = rotl32(x1, 13); x1 ^= x0;
    x0 += x1; x1 = rotl32(x1, 15); x1 ^= x0;
    x0 += x1; x1 = rotl32(x1, 26); x1 ^= x0;
    x0 += x1; x1 = rotl32(x1,  6); x1 ^= x0;
    x0 += ks0; x1 += ks1 + 3u;
    x0 += x1; x1 = rotl32(x1, 17); x1 ^= x0;
    x0 += x1; x1 = rotl32(x1, 29); x1 ^= x0;
    x0 += x1; x1 = rotl32(x1, 16); x1 ^= x0;
    x0 += x1; x1 = rotl32(x1, 24); x1 ^= x0;
    x0 += ks1; x1 += ks2 + 4u;
    x0 += x1; x1 = rotl32(x1, 13); x1 ^= x0;
    x0 += x1; x1 = rotl32(x1, 15); x1 ^= x0;
    x0 += x1; x1 = rotl32(x1, 26); x1 ^= x0;
    x0 += x1; x1 = rotl32(x1,  6); x1 ^= x0;
    x0 += ks2; x1 += ks0 + 5u;
    return {x0, x1};
}
constexpr U2 RK1 = threefry2x32(0u, 42u, 0u, 0u);
constexpr U2 RK2 = threefry2x32(0u, 42u, 0u, 1u);

__device__ __forceinline__ float bits_to_uniform(uint32_t bits) {
    return __uint_as_float((bits >> 9) | 0x3f800000u) - 1.0f;
}

// ---------------- grid geometry ----------------
struct GridGeom { float x0, y0, z0, invh, h; };
__device__ __forceinline__ GridGeom load_geom(const unsigned* bbox, int G) {
    GridGeom g;
    g.x0 = o2f(bbox[0]); g.y0 = o2f(bbox[1]); g.z0 = o2f(bbox[2]);
    float ex = o2f(bbox[3]) - g.x0;
    float ey = o2f(bbox[4]) - g.y0;
    float ez = o2f(bbox[5]) - g.z0;
    float e = fmaxf(fmaxf(ex, ey), fmaxf(ez, 1e-20f));
    g.h = e / (float)G;
    g.invh = (float)G / e;
    return g;
}
__device__ __forceinline__ int cell_coord(float v, float v0, float invh, int G) {
    int c = (int)((v - v0) * invh);
    return min(max(c, 0), G - 1);
}

// ---------------- exact expanding-shell 1-NN, one thread per query ---------
template <int G>
__device__ __forceinline__ float shell_nn(float qx, float qy, float qz, float qw,
                                          const GridGeom g,
                                          const int* __restrict__ cellstart,
                                          const float4* __restrict__ sorted) {
    float m2x = -2.0f * qx, m2y = -2.0f * qy, m2z = -2.0f * qz;
    int cx = cell_coord(qx, g.x0, g.invh, G);
    int cy = cell_coord(qy, g.y0, g.invh, G);
    int cz = cell_coord(qz, g.z0, g.invh, G);

    float best = 3.0e38f;
    for (int R = 0; R <= G; R++) {
        if (R > 0) {
            float lb = (float)(R - 1) * g.h;
            if (best + qw <= lb * lb) break;
        }
        int zlo = max(cz - R, 0), zhi = min(cz + R, G - 1);
        int ylo = max(cy - R, 0), yhi = min(cy + R, G - 1);
        int xlo = max(cx - R, 0), xhi = min(cx + R, G - 1);
        for (int z = zlo; z <= zhi; z++) {
            bool ze = (z == cz - R) || (z == cz + R);
            for (int y = ylo; y <= yhi; y++) {
                bool edge = ze || (y == cy - R) || (y == cy + R);
                int rowbase = (z * G + y) * G;
                if (edge) {
                    int p0 = __ldg(&cellstart[rowbase + xlo]);
                    int p1 = __ldg(&cellstart[rowbase + xhi + 1]);
                    for (int p = p0; p < p1; p++) {
                        float4 v = sorted[p];
                        float t = fmaf(v.x, m2x, fmaf(v.y, m2y, fmaf(v.z, m2z, v.w)));
                        best = fminf(best, t);
                    }
                } else {
                    int xa = cx - R, xb = cx + R;
                    if (xa >= 0) {
                        int c0 = rowbase + xa;
                        int p0 = __ldg(&cellstart[c0]), p1 = __ldg(&cellstart[c0 + 1]);
                        for (int p = p0; p < p1; p++) {
                            float4 v = sorted[p];
                            float t = fmaf(v.x, m2x, fmaf(v.y, m2y, fmaf(v.z, m2z, v.w)));
                            best = fminf(best, t);
                        }
                    }
                    if (xb <= G - 1) {
                        int c0 = rowbase + xb;
                        int p0 = __ldg(&cellstart[c0]), p1 = __ldg(&cellstart[c0 + 1]);
                        for (int p = p0; p < p1; p++) {
                            float4 v = sorted[p];
                            float t = fmaf(v.x, m2x, fmaf(v.y, m2y, fmaf(v.z, m2z, v.w)));
                            best = fminf(best, t);
                        }
                    }
                }
            }
        }
        if (zlo == 0 && ylo == 0 && xlo == 0 &&
            zhi == G - 1 && yhi == G - 1 && xhi == G - 1) break;
    }
    return fmaxf(best + qw, 0.0f);
}

// ---------------- kernel A: fused init + prep ----------------
__global__ void init_prep_kernel(const float* __restrict__ ov,
                                 const int*   __restrict__ of,
                                 const float* __restrict__ sv,
                                 const int*   __restrict__ sf) {
    int i = blockIdx.x * 256 + threadIdx.x;
    if (i < NCELLS)  { g_count[i] = 0;  g_cursor[i] = 0;
                       g_count3[i] = 0; g_cursor3[i] = 0; }
    if (i < NCELLS2) { g_count2[i] = 0; g_cursor2[i] = 0; }
    if (i == 0) {
        g_maxbits = 0u;
        for (int k = 0; k < 3; k++) { g_bbox[k] = 0xFFFFFFFFu;  g_bbox[k + 3] = 0u; }
        for (int k = 0; k < 3; k++) { g_bbox2[k] = 0xFFFFFFFFu; g_bbox2[k + 3] = 0u; }
    }

    // bbox of original vertices
    {
        float mnx =  3.0e38f, mxx = -3.0e38f;
        float mny =  3.0e38f, mxy = -3.0e38f;
        float mnz =  3.0e38f, mxz = -3.0e38f;
        if (i < N_OV) {
            mnx = mxx = ov[3 * i];
            mny = mxy = ov[3 * i + 1];
            mnz = mxz = ov[3 * i + 2];
        }
#pragma unroll
        for (int o = 16; o > 0; o >>= 1) {
            mnx = fminf(mnx, __shfl_xor_sync(0xffffffffu, mnx, o));
            mny = fminf(mny, __shfl_xor_sync(0xffffffffu, mny, o));
            mnz = fminf(mnz, __shfl_xor_sync(0xffffffffu, mnz, o));
            mxx = fmaxf(mxx, __shfl_xor_sync(0xffffffffu, mxx, o));
            mxy = fmaxf(mxy, __shfl_xor_sync(0xffffffffu, mxy, o));
            mxz = fmaxf(mxz, __shfl_xor_sync(0xffffffffu, mxz, o));
        }
        if ((threadIdx.x & 31) == 0 && (blockIdx.x * 256 + (threadIdx.x & ~31)) < N_OV) {
            atomicMin(&g_bbox[0], f2o(mnx));
            atomicMin(&g_bbox[1], f2o(mny));
            atomicMin(&g_bbox[2], f2o(mnz));
            atomicMax(&g_bbox[3], f2o(mxx));
            atomicMax(&g_bbox[4], f2o(mxy));
            atomicMax(&g_bbox[5], f2o(mxz));
        }
    }
    // original barycenters + their bbox
    {
        float bx, by, bz;
        float mnx =  3.0e38f, mxx = -3.0e38f;
        float mny =  3.0e38f, mxy = -3.0e38f;
        float mnz =  3.0e38f, mxz = -3.0e38f;
        if (i < N_OF) {
            int f0 = of[3 * i], f1 = of[3 * i + 1], f2 = of[3 * i + 2];
            bx = (ov[3 * f0] + ov[3 * f1] + ov[3 * f2]) / 3.0f;
            by = (ov[3 * f0 + 1] + ov[3 * f1 + 1] + ov[3 * f2 + 1]) / 3.0f;
            bz = (ov[3 * f0 + 2] + ov[3 * f1 + 2] + ov[3 * f2 + 2]) / 3.0f;
            g_obp[i] = make_float4(bx, by, bz, bx * bx + by * by + bz * bz);
            mnx = mxx = bx; mny = mxy = by; mnz = mxz = bz;
        }
#pragma unroll
        for (int o = 16; o > 0; o >>= 1) {
            mnx = fminf(mnx, __shfl_xor_sync(0xffffffffu, mnx, o));
            mny = fminf(mny, __shfl_xor_sync(0xffffffffu, mny, o));
            mnz = fminf(mnz, __shfl_xor_sync(0xffffffffu, mnz, o));
            mxx = fmaxf(mxx, __shfl_xor_sync(0xffffffffu, mxx, o));
            mxy = fmaxf(mxy, __shfl_xor_sync(0xffffffffu, mxy, o));
            mxz = fmaxf(mxz, __shfl_xor_sync(0xffffffffu, mxz, o));
        }
        if ((threadIdx.x & 31) == 0 && (blockIdx.x * 256 + (threadIdx.x & ~31)) < N_OF) {
            atomicMin(&g_bbox2[0], f2o(mnx));
            atomicMin(&g_bbox2[1], f2o(mny));
            atomicMin(&g_bbox2[2], f2o(mnz));
            atomicMax(&g_bbox2[3], f2o(mxx));
            atomicMax(&g_bbox2[4], f2o(mxy));
            atomicMax(&g_bbox2[5], f2o(mxz));
        }
    }
    if (i < N_SF) {
        int f0 = sf[3 * i], f1 = sf[3 * i + 1], f2 = sf[3 * i + 2];
        float bx = (sv[3 * f0] + sv[3 * f1] + sv[3 * f2]) / 3.0f;
        float by = (sv[3 * f0 + 1] + sv[3 * f1 + 1] + sv[3 * f2 + 1]) / 3.0f;
        float bz = (sv[3 * f0 + 2] + sv[3 * f1 + 2] + sv[3 * f2 + 2]) / 3.0f;
        g_sb[i] = make_float4(bx, by, bz, bx * bx + by * by + bz * bz);
    }
}

// ---------------- kernel C: sample generation + cell count ----------------
__global__ void gen_samples_kernel(const float* __restrict__ sv,
                                   const int*   __restrict__ sf) {
    int j = blockIdx.x * 256 + threadIdx.x;
    if (j >= N_SAMPLES) return;

    U2 ua = threefry2x32(RK1.a, RK1.b, 0u, (uint32_t)j);
    U2 ub = threefry2x32(RK2.a, RK2.b, 0u, (uint32_t)j);

    float u1 = bits_to_uniform(ua.a ^ ua.b);
    float r2 = bits_to_uniform(ub.a ^ ub.b);
    float sq = sqrtf(u1);
    float a = 1.0f - sq;
    float b = sq * (1.0f - r2);
    float c = sq * r2;
    int f = j / NSAMP;
    int i0 = sf[3 * f], i1 = sf[3 * f + 1], i2 = sf[3 * f + 2];
    float x = a * sv[3 * i0]     + b * sv[3 * i1]     + c * sv[3 * i2];
    float y = a * sv[3 * i0 + 1] + b * sv[3 * i1 + 1] + c * sv[3 * i2 + 1];
    float z = a * sv[3 * i0 + 2] + b * sv[3 * i1 + 2] + c * sv[3 * i2 + 2];
    g_samples[j] = make_float4(x, y, z, x * x + y * y + z * z);

    GridGeom g = load_geom(g_bbox, GRID_G);
    int cx = cell_coord(x, g.x0, g.invh, GRID_G);
    int cy = cell_coord(y, g.y0, g.invh, GRID_G);
    int cz = cell_coord(z, g.z0, g.invh, GRID_G);
    atomicAdd(&g_count3[(cz * GRID_G + cy) * GRID_G + cx], 1);
}

// ---------------- kernel D1: count (vertex + barycenter grids) -------------
__global__ void count_kernel(const float* __restrict__ ov) {
    int i = blockIdx.x * 256 + threadIdx.x;
    if (i < N_OV) {
        GridGeom g = load_geom(g_bbox, GRID_G);
        int cx = cell_coord(ov[3 * i],     g.x0, g.invh, GRID_G);
        int cy = cell_coord(ov[3 * i + 1], g.y0, g.invh, GRID_G);
        int cz = cell_coord(ov[3 * i + 2], g.z0, g.invh, GRID_G);
        atomicAdd(&g_count[(cz * GRID_G + cy) * GRID_G + cx], 1);
    }
    if (i < N_OF) {
        GridGeom g = load_geom(g_bbox2, GRID_G2);
        float4 b = g_obp[i];
        int cx = cell_coord(b.x, g.x0, g.invh, GRID_G2);
        int cy = cell_coord(b.y, g.y0, g.invh, GRID_G2);
        int cz = cell_coord(b.z, g.z0, g.invh, GRID_G2);
        atomicAdd(&g_count2[(cz * GRID_G2 + cy) * GRID_G2 + cx], 1);
    }
}

// ---------------- scan helper ----------------
__device__ __forceinline__ void block_scan_1024(const int* __restrict__ cnt_arr,
                                                int* __restrict__ start_arr,
                                                int* __restrict__ bsum_arr,
                                                int seg_block) {
    __shared__ int sd[1024];
    int tid = threadIdx.x;
    int cell = seg_block * 1024 + tid;
    int cnt = cnt_arr[cell];
    sd[tid] = cnt;
    __syncthreads();
#pragma unroll
    for (int off = 1; off < 1024; off <<= 1) {
        int v = (tid >= off) ? sd[tid - off] : 0;
        __syncthreads();
        sd[tid] += v;
        __syncthreads();
    }
    start_arr[cell] = sd[tid] - cnt;
    if (tid == 1023) bsum_arr[seg_block] = sd[1023];
}

// ---------------- kernel D2: block-level scans (3 grids) ----------------
__global__ void __launch_bounds__(1024) scan1_kernel() {
    int b = blockIdx.x;
    if (b < SCAN_BLOCKS) {
        block_scan_1024(g_count, g_cellstart, g_blocksum, b);
    } else if (b < SCAN_BLOCKS + SCAN_BLOCKS2) {
        block_scan_1024(g_count2, g_cellstart2, g_blocksum2, b - SCAN_BLOCKS);
    } else {
        block_scan_1024(g_count3, g_cellstart3, g_blocksum3, b - SCAN_BLOCKS - SCAN_BLOCKS2);
    }
}

// ---------------- kernel D3: scan of block sums (3 grids) ----------------
__global__ void __launch_bounds__(256) scan2_kernel() {
    __shared__ int sd[SCAN_BLOCKS];
    int tid = threadIdx.x;
    // grid V
    {
        int v = g_blocksum[tid];
        sd[tid] = v;
        __syncthreads();
#pragma unroll
        for (int off = 1; off < SCAN_BLOCKS; off <<= 1) {
            int w = (tid >= off) ? sd[tid - off] : 0;
            __syncthreads();
            sd[tid] += w;
            __syncthreads();
        }
        g_blockoff[tid] = sd[tid] - v;
        if (tid == SCAN_BLOCKS - 1) g_cellstart[NCELLS] = sd[tid];
        __syncthreads();
    }
    // grid S
    {
        int v = g_blocksum3[tid];
        sd[tid] = v;
        __syncthreads();
#pragma unroll
        for (int off = 1; off < SCAN_BLOCKS; off <<= 1) {
            int w = (tid >= off) ? sd[tid - off] : 0;
            __syncthreads();
            sd[tid] += w;
            __syncthreads();
        }
        g_blockoff3[tid] = sd[tid] - v;
        if (tid == SCAN_BLOCKS - 1) g_cellstart3[NCELLS] = sd[tid];
        __syncthreads();
    }
    // grid B: 32 sums, warp scan
    if (tid < 32) {
        int v2 = g_blocksum2[tid];
        int s = v2;
#pragma unroll
        for (int off = 1; off < 32; off <<= 1) {
            int w = __shfl_up_sync(0xffffffffu, s, off);
            if ((int)(threadIdx.x & 31) >= off) s += w;
        }
        g_blockoff2[tid] = s - v2;
        if (tid == 31) g_cellstart2[NCELLS2] = s;
    }
}

// ---------------- kernel D4: add block offsets (3 grids) ----------------
__global__ void __launch_bounds__(1024) scan3_kernel() {
    int b = blockIdx.x;
    int tid = threadIdx.x;
    if (b < SCAN_BLOCKS) {
        g_cellstart[b * 1024 + tid] += g_blockoff[b];
    } else if (b < SCAN_BLOCKS + SCAN_BLOCKS2) {
        int bb = b - SCAN_BLOCKS;
        g_cellstart2[bb * 1024 + tid] += g_blockoff2[bb];
    } else {
        int bb = b - SCAN_BLOCKS - SCAN_BLOCKS2;
        g_cellstart3[bb * 1024 + tid] += g_blockoff3[bb];
    }
}

// ---------------- kernel D5: scatter (vertices, barycenters, samples) ------
__global__ void scatter_kernel(const float* __restrict__ ov,
                               const float* __restrict__ fp) {
    int i = blockIdx.x * 256 + threadIdx.x;
    if (i < N_OV) {
        GridGeom g = load_geom(g_bbox, GRID_G);
        float x = ov[3 * i], y = ov[3 * i + 1], z = ov[3 * i + 2];
        int cx = cell_coord(x, g.x0, g.invh, GRID_G);
        int cy = cell_coord(y, g.y0, g.invh, GRID_G);
        int cz = cell_coord(z, g.z0, g.invh, GRID_G);
        int c = (cz * GRID_G + cy) * GRID_G + cx;
        int pos = g_cellstart[c] + atomicAdd(&g_cursor[c], 1);
        g_sorted[pos] = make_float4(x, y, z, x * x + y * y + z * z);
    }
    if (i < N_OF) {
        GridGeom g = load_geom(g_bbox2, GRID_G2);
        float4 b = g_obp[i];
        int cx = cell_coord(b.x, g.x0, g.invh, GRID_G2);
        int cy = cell_coord(b.y, g.y0, g.invh, GRID_G2);
        int cz = cell_coord(b.z, g.z0, g.invh, GRID_G2);
        int c = (cz * GRID_G2 + cy) * GRID_G2 + cx;
        int pos = g_cellstart2[c] + atomicAdd(&g_cursor2[c], 1);
        g_sorted2[pos] = b;
    }
    if (i < N_SAMPLES) {
        GridGeom g = load_geom(g_bbox, GRID_G);
        float4 s = g_samples[i];
        int cx = cell_coord(s.x, g.x0, g.invh, GRID_G);
        int cy = cell_coord(s.y, g.y0, g.invh, GRID_G);
        int cz = cell_coord(s.z, g.z0, g.invh, GRID_G);
        int c = (cz * GRID_G + cy) * GRID_G + cx;
        int pos = g_cellstart3[c] + atomicAdd(&g_cursor3[c], 1);
        g_ssorted[pos] = s;
        g_sfp[pos] = fp[i / NSAMP];
    }
}

// ---------------- kernel E1: forward 1-NN, one WARP per query --------------
__global__ void __launch_bounds__(256) forward_warp_kernel() {
    int warp = (blockIdx.x * 256 + threadIdx.x) >> 5;
    int lane = threadIdx.x & 31;
    if (warp >= N_SF) return;

    GridGeom g = load_geom(g_bbox2, GRID_G2);
    float4 Q = g_sb[warp];
    float m2x = -2.0f * Q.x, m2y = -2.0f * Q.y, m2z = -2.0f * Q.z;
    int cx = cell_coord(Q.x, g.x0, g.invh, GRID_G2);
    int cy = cell_coord(Q.y, g.y0, g.invh, GRID_G2);
    int cz = cell_coord(Q.z, g.z0, g.invh, GRID_G2);
    const int G = GRID_G2;

    float best = 3.0e38f;
    for (int R = 0; R <= G; R++) {
        float bmin = best;
#pragma unroll
        for (int o = 16; o > 0; o >>= 1)
            bmin = fminf(bmin, __shfl_xor_sync(0xffffffffu, bmin, o));
        if (R > 0) {
            float lb = (float)(R - 1) * g.h;
            if (bmin + Q.w <= lb * lb) break;
        }
        int zlo = max(cz - R, 0), zhi = min(cz + R, G - 1);
        int ylo = max(cy - R, 0), yhi = min(cy + R, G - 1);
        int xlo = max(cx - R, 0), xhi = min(cx + R, G - 1);
        for (int z = zlo; z <= zhi; z++) {
            bool ze = (z == cz - R) || (z == cz + R);
            for (int y = ylo; y <= yhi; y++) {
                bool edge = ze || (y == cy - R) || (y == cy + R);
                int rowbase = (z * G + y) * G;
                if (edge) {
                    int p0 = __ldg(&g_cellstart2[rowbase + xlo]);
                    int p1 = __ldg(&g_cellstart2[rowbase + xhi + 1]);
                    for (int p = p0 + lane; p < p1; p += 32) {
                        float4 v = g_sorted2[p];
                        float t = fmaf(v.x, m2x, fmaf(v.y, m2y, fmaf(v.z, m2z, v.w)));
                        best = fminf(best, t);
                    }
                } else {
                    int xa = cx - R, xb = cx + R;
                    if (xa >= 0) {
                        int c0 = rowbase + xa;
                        int p0 = __ldg(&g_cellstart2[c0]), p1 = __ldg(&g_cellstart2[c0 + 1]);
                        for (int p = p0 + lane; p < p1; p += 32) {
                            float4 v = g_sorted2[p];
                            float t = fmaf(v.x, m2x, fmaf(v.y, m2y, fmaf(v.z, m2z, v.w)));
                            best = fminf(best, t);
                        }
                    }
                    if (xb <= G - 1) {
                        int c0 = rowbase + xb;
                        int p0 = __ldg(&g_cellstart2[c0]), p1 = __ldg(&g_cellstart2[c0 + 1]);
                        for (int p = p0 + lane; p < p1; p += 32) {
                            float4 v = g_sorted2[p];
                            float t = fmaf(v.x, m2x, fmaf(v.y, m2y, fmaf(v.z, m2z, v.w)));
                            best = fminf(best, t);
                        }
                    }
                }
            }
        }
        if (zlo == 0 && ylo == 0 && xlo == 0 &&
            zhi == G - 1 && yhi == G - 1 && xhi == G - 1) break;
    }
    float bmin = best;
#pragma unroll
    for (int o = 16; o > 0; o >>= 1)
        bmin = fminf(bmin, __shfl_xor_sync(0xffffffffu, bmin, o));
    if (lane == 0)
        g_minfwd[warp] = __float_as_uint(fmaxf(bmin + Q.w, 0.0f));
}

// ---------------- kernel E2: reverse 1-NN on cell-sorted samples -----------
__global__ void __launch_bounds__(256) reverse_sorted_kernel() {
    int j = blockIdx.x * 256 + threadIdx.x;

    float d = 0.0f;
    double contrib = 0.0;
    if (j < N_SAMPLES) {
        GridGeom g = load_geom(g_bbox, GRID_G);
        float4 s = g_ssorted[j];
        float d2 = shell_nn<GRID_G>(s.x, s.y, s.z, s.w, g, g_cellstart, g_sorted);
        d = sqrtf(d2);
        contrib = (double)(g_sfp[j] * d);
    }

    __shared__ double rsum[256];
    __shared__ float rmax[256];
    int tid = threadIdx.x;
    rsum[tid] = contrib;
    rmax[tid] = d;
    __syncthreads();
#pragma unroll
    for (int o = 128; o > 0; o >>= 1) {
        if (tid < o) {
            rsum[tid] += rsum[tid + o];
            rmax[tid] = fmaxf(rmax[tid], rmax[tid + o]);
        }
        __syncthreads();
    }
    if (tid == 0) {
        g_part[blockIdx.x] = rsum[0];
        atomicMax(&g_maxbits, __float_as_uint(rmax[0]));
    }
}

// ---------------- kernel F: final ----------------
__global__ void __launch_bounds__(512) final_kernel(const float* __restrict__ fp,
                                                    float* __restrict__ out) {
    __shared__ double red[512];
    int tid = threadIdx.x;

    double fwd = 0.0, pen = 0.0, rev = 0.0;
    for (int i = tid; i < N_SF; i += 512) {
        float p = fp[i];
        float d2 = __uint_as_float(g_minfwd[i]);
        fwd += (double)(p * sqrtf(d2));
        pen += (double)(1.0f - p);
    }
    for (int b = tid; b < REV_BLOCKS; b += 512) rev += g_part[b];

    double totF, totP, totR;
    red[tid] = fwd; __syncthreads();
    for (int o = 256; o > 0; o >>= 1) { if (tid < o) red[tid] += red[tid + o]; __syncthreads(); }
    totF = red[0]; __syncthreads();
    red[tid] = pen; __syncthreads();
    for (int o = 256; o > 0; o >>= 1) { if (tid < o) red[tid] += red[tid + o]; __syncthreads(); }
    totP = red[0]; __syncthreads();
    red[tid] = rev; __syncthreads();
    for (int o = 256; o > 0; o >>= 1) { if (tid < o) red[tid] += red[tid + o]; __syncthreads(); }
    totR = red[0];

    if (tid == 0) {
        double maxd = (double)__uint_as_float(g_maxbits);
        double result = totF + 1e-4 * totP + totR / (maxd + 1e-8) * 0.1;
        out[0] = (float)result;
    }
}

// ---------------- launch ----------------
extern "C" void kernel_launch(void* const* d_in, const int* in_sizes, int n_in,
                              void* d_out, int out_size) {
    const float* ov = (const float*)d_in[0];
    const int*   of = (const int*)  d_in[1];
    const float* sv = (const float*)d_in[2];
    const int*   sf = (const int*)  d_in[3];
    const float* fp = (const float*)d_in[4];
    float* out = (float*)d_out;

    init_prep_kernel<<<(NCELLS + 255) / 256, 256>>>(ov, of, sv, sf);
    gen_samples_kernel<<<(N_SAMPLES + 255) / 256, 256>>>(sv, sf);

    count_kernel<<<(N_OF + 255) / 256, 256>>>(ov);
    scan1_kernel<<<2 * SCAN_BLOCKS + SCAN_BLOCKS2, 1024>>>();
    scan2_kernel<<<1, 256>>>();
    scan3_kernel<<<2 * SCAN_BLOCKS + SCAN_BLOCKS2, 1024>>>();
    scatter_kernel<<<(N_SAMPLES + 255) / 256, 256>>>(ov, fp);

    forward_warp_kernel<<<FWD_WARP_BLOCKS, 256>>>();
    reverse_sorted_kernel<<<REV_BLOCKS, 256>>>();
    final_kernel<<<1, 512>>>(fp, out);
}

// round 10
// speedup vs baseline: 1.6595x; 1.1654x over previous
#include <cuda_runtime.h>
#include <cuda_bf16.h>
#include <stdint.h>

// ---------------- problem constants (static shapes) ----------------
#define N_OV 20000
#define N_OF 30000
#define N_SV 4000
#define N_SF 5000
#define NSAMP 50
#define N_SAMPLES 250000
// vertex grid (reverse term) — also used to sort samples
#define GRID_G 32
#define NCELLS (GRID_G * GRID_G * GRID_G)       // 32768
#define SCAN_BLOCKS 32
// barycenter grid (forward term)
#define GRID_G2 32
#define NCELLS2 (GRID_G2 * GRID_G2 * GRID_G2)   // 32768
#define SCAN_BLOCKS2 32
#define REV_BLOCKS 977                           // ceil(250000/256)
#define FWD_WARP_BLOCKS 625                      // 5000 warps
#define GEN_BLOCKS 977                           // covers N_SAMPLES, N_OV, N_OF

// ---------------- device scratch (static, no runtime alloc) ----------------
__device__ float4    g_obp[N_OF];
__device__ float4    g_sb[N_SF];
__device__ unsigned  g_minfwd[N_SF];
__device__ float4    g_samples[N_SAMPLES];      // unsorted
__device__ float4    g_ssorted[N_SAMPLES];      // cell-sorted samples
__device__ float     g_sfp[N_SAMPLES];          // fp aligned to sorted order
__device__ unsigned  g_maxbits;
__device__ double    g_part[REV_BLOCKS];
// grid V (vertices)
__device__ unsigned  g_bbox[6];
__device__ int       g_count[NCELLS];
__device__ int       g_cursor[NCELLS];
__device__ int       g_cellstart[NCELLS + 1];
__device__ int       g_blocksum[SCAN_BLOCKS];
__device__ int       g_blockoff[SCAN_BLOCKS];
__device__ float4    g_sorted[N_OV];
// grid B (original barycenters)
__device__ unsigned  g_bbox2[6];
__device__ int       g_count2[NCELLS2];
__device__ int       g_cursor2[NCELLS2];
__device__ int       g_cellstart2[NCELLS2 + 1];
__device__ int       g_blocksum2[SCAN_BLOCKS2];
__device__ int       g_blockoff2[SCAN_BLOCKS2];
__device__ float4    g_sorted2[N_OF];
// grid S (samples, same geometry as grid V)
__device__ int       g_count3[NCELLS];
__device__ int       g_cursor3[NCELLS];
__device__ int       g_cellstart3[NCELLS + 1];
__device__ int       g_blocksum3[SCAN_BLOCKS];
__device__ int       g_blockoff3[SCAN_BLOCKS];

// ---------------- ordered-float helpers ----------------
__device__ __forceinline__ unsigned f2o(float f) {
    unsigned u = __float_as_uint(f);
    return (u & 0x80000000u) ? ~u : (u | 0x80000000u);
}
__device__ __forceinline__ float o2f(unsigned u) {
    u = (u & 0x80000000u) ? (u & 0x7fffffffu) : ~u;
    return __uint_as_float(u);
}

// ---------------- threefry2x32 (JAX partitionable, 20 rounds) ----------------
__host__ __device__ constexpr uint32_t rotl32(uint32_t x, int r) {
    return (x << r) | (x >> (32 - r));
}
struct U2 { uint32_t a, b; };
__host__ __device__ constexpr U2 threefry2x32(uint32_t k0, uint32_t k1,
                                              uint32_t x0, uint32_t x1) {
    uint32_t ks0 = k0, ks1 = k1, ks2 = k0 ^ k1 ^ 0x1BD11BDAu;
    x0 += ks0; x1 += ks1;
    x0 += x1; x1 = rotl32(x1, 13); x1 ^= x0;
    x0 += x1; x1 = rotl32(x1, 15); x1 ^= x0;
    x0 += x1; x1 = rotl32(x1, 26); x1 ^= x0;
    x0 += x1; x1 = rotl32(x1,  6); x1 ^= x0;
    x0 += ks1; x1 += ks2 + 1u;
    x0 += x1; x1 = rotl32(x1, 17); x1 ^= x0;
    x0 += x1; x1 = rotl32(x1, 29); x1 ^= x0;
    x0 += x1; x1 = rotl32(x1, 16); x1 ^= x0;
    x0 += x1; x1 = rotl32(x1, 24); x1 ^= x0;
    x0 += ks2; x1 += ks0 + 2u;
    x0 += x1; x1 = rotl32(x1, 13); x1 ^= x0;
    x0 += x1; x1 = rotl32(x1, 15); x1 ^= x0;
    x0 += x1; x1 = rotl32(x1, 26); x1 ^= x0;
    x0 += x1; x1 = rotl32(x1,  6); x1 ^= x0;
    x0 += ks0; x1 += ks1 + 3u;
    x0 += x1; x1 = rotl32(x1, 17); x1 ^= x0;
    x0 += x1; x1 = rotl32(x1, 29); x1 ^= x0;
    x0 += x1; x1 = rotl32(x1, 16); x1 ^= x0;
    x0 += x1; x1 = rotl32(x1, 24); x1 ^= x0;
    x0 += ks1; x1 += ks2 + 4u;
    x0 += x1; x1 = rotl32(x1, 13); x1 ^= x0;
    x0 += x1; x1 = rotl32(x1, 15); x1 ^= x0;
    x0 += x1; x1 = rotl32(x1, 26); x1 ^= x0;
    x0 += x1; x1 = rotl32(x1,  6); x1 ^= x0;
    x0 += ks2; x1 += ks0 + 5u;
    return {x0, x1};
}
constexpr U2 RK1 = threefry2x32(0u, 42u, 0u, 0u);
constexpr U2 RK2 = threefry2x32(0u, 42u, 0u, 1u);

__device__ __forceinline__ float bits_to_uniform(uint32_t bits) {
    return __uint_as_float((bits >> 9) | 0x3f800000u) - 1.0f;
}

// ---------------- grid geometry ----------------
struct GridGeom { float x0, y0, z0, invh, h; };
__device__ __forceinline__ GridGeom load_geom(const unsigned* bbox, int G) {
    GridGeom g;
    g.x0 = o2f(bbox[0]); g.y0 = o2f(bbox[1]); g.z0 = o2f(bbox[2]);
    float ex = o2f(bbox[3]) - g.x0;
    float ey = o2f(bbox[4]) - g.y0;
    float ez = o2f(bbox[5]) - g.z0;
    float e = fmaxf(fmaxf(ex, ey), fmaxf(ez, 1e-20f));
    g.h = e / (float)G;
    g.invh = (float)G / e;
    return g;
}
__device__ __forceinline__ int cell_coord(float v, float v0, float invh, int G) {
    int c = (int)((v - v0) * invh);
    return min(max(c, 0), G - 1);
}

// ---------------- exact expanding-shell 1-NN, one thread per query ---------
template <int G>
__device__ __forceinline__ float shell_nn(float qx, float qy, float qz, float qw,
                                          const GridGeom g,
                                          const int* __restrict__ cellstart,
                                          const float4* __restrict__ sorted) {
    float m2x = -2.0f * qx, m2y = -2.0f * qy, m2z = -2.0f * qz;
    int cx = cell_coord(qx, g.x0, g.invh, G);
    int cy = cell_coord(qy, g.y0, g.invh, G);
    int cz = cell_coord(qz, g.z0, g.invh, G);

    float best = 3.0e38f;
    for (int R = 0; R <= G; R++) {
        if (R > 0) {
            float lb = (float)(R - 1) * g.h;
            if (best + qw <= lb * lb) break;
        }
        int zlo = max(cz - R, 0), zhi = min(cz + R, G - 1);
        int ylo = max(cy - R, 0), yhi = min(cy + R, G - 1);
        int xlo = max(cx - R, 0), xhi = min(cx + R, G - 1);
        for (int z = zlo; z <= zhi; z++) {
            bool ze = (z == cz - R) || (z == cz + R);
            for (int y = ylo; y <= yhi; y++) {
                bool edge = ze || (y == cy - R) || (y == cy + R);
                int rowbase = (z * G + y) * G;
                if (edge) {
                    int p0 = __ldg(&cellstart[rowbase + xlo]);
                    int p1 = __ldg(&cellstart[rowbase + xhi + 1]);
                    for (int p = p0; p < p1; p++) {
                        float4 v = sorted[p];
                        float t = fmaf(v.x, m2x, fmaf(v.y, m2y, fmaf(v.z, m2z, v.w)));
                        best = fminf(best, t);
                    }
                } else {
                    int xa = cx - R, xb = cx + R;
                    if (xa >= 0) {
                        int c0 = rowbase + xa;
                        int p0 = __ldg(&cellstart[c0]), p1 = __ldg(&cellstart[c0 + 1]);
                        for (int p = p0; p < p1; p++) {
                            float4 v = sorted[p];
                            float t = fmaf(v.x, m2x, fmaf(v.y, m2y, fmaf(v.z, m2z, v.w)));
                            best = fminf(best, t);
                        }
                    }
                    if (xb <= G - 1) {
                        int c0 = rowbase + xb;
                        int p0 = __ldg(&cellstart[c0]), p1 = __ldg(&cellstart[c0 + 1]);
                        for (int p = p0; p < p1; p++) {
                            float4 v = sorted[p];
                            float t = fmaf(v.x, m2x, fmaf(v.y, m2y, fmaf(v.z, m2z, v.w)));
                            best = fminf(best, t);
                        }
                    }
                }
            }
        }
        if (zlo == 0 && ylo == 0 && xlo == 0 &&
            zhi == G - 1 && yhi == G - 1 && xhi == G - 1) break;
    }
    return fmaxf(best + qw, 0.0f);
}

// ---------------- kernel A: fused init + prep ----------------
__global__ void init_prep_kernel(const float* __restrict__ ov,
                                 const int*   __restrict__ of,
                                 const float* __restrict__ sv,
                                 const int*   __restrict__ sf) {
    int i = blockIdx.x * 256 + threadIdx.x;
    if (i < NCELLS)  { g_count[i] = 0;  g_cursor[i] = 0;
                       g_count3[i] = 0; g_cursor3[i] = 0; }
    if (i < NCELLS2) { g_count2[i] = 0; g_cursor2[i] = 0; }
    if (i == 0) {
        g_maxbits = 0u;
        for (int k = 0; k < 3; k++) { g_bbox[k] = 0xFFFFFFFFu;  g_bbox[k + 3] = 0u; }
        for (int k = 0; k < 3; k++) { g_bbox2[k] = 0xFFFFFFFFu; g_bbox2[k + 3] = 0u; }
    }

    // bbox of original vertices
    {
        float mnx =  3.0e38f, mxx = -3.0e38f;
        float mny =  3.0e38f, mxy = -3.0e38f;
        float mnz =  3.0e38f, mxz = -3.0e38f;
        if (i < N_OV) {
            mnx = mxx = ov[3 * i];
            mny = mxy = ov[3 * i + 1];
            mnz = mxz = ov[3 * i + 2];
        }
#pragma unroll
        for (int o = 16; o > 0; o >>= 1) {
            mnx = fminf(mnx, __shfl_xor_sync(0xffffffffu, mnx, o));
            mny = fminf(mny, __shfl_xor_sync(0xffffffffu, mny, o));
            mnz = fminf(mnz, __shfl_xor_sync(0xffffffffu, mnz, o));
            mxx = fmaxf(mxx, __shfl_xor_sync(0xffffffffu, mxx, o));
            mxy = fmaxf(mxy, __shfl_xor_sync(0xffffffffu, mxy, o));
            mxz = fmaxf(mxz, __shfl_xor_sync(0xffffffffu, mxz, o));
        }
        if ((threadIdx.x & 31) == 0 && (blockIdx.x * 256 + (threadIdx.x & ~31)) < N_OV) {
            atomicMin(&g_bbox[0], f2o(mnx));
            atomicMin(&g_bbox[1], f2o(mny));
            atomicMin(&g_bbox[2], f2o(mnz));
            atomicMax(&g_bbox[3], f2o(mxx));
            atomicMax(&g_bbox[4], f2o(mxy));
            atomicMax(&g_bbox[5], f2o(mxz));
        }
    }
    // original barycenters + their bbox
    {
        float bx, by, bz;
        float mnx =  3.0e38f, mxx = -3.0e38f;
        float mny =  3.0e38f, mxy = -3.0e38f;
        float mnz =  3.0e38f, mxz = -3.0e38f;
        if (i < N_OF) {
            int f0 = of[3 * i], f1 = of[3 * i + 1], f2 = of[3 * i + 2];
            bx = (ov[3 * f0] + ov[3 * f1] + ov[3 * f2]) / 3.0f;
            by = (ov[3 * f0 + 1] + ov[3 * f1 + 1] + ov[3 * f2 + 1]) / 3.0f;
            bz = (ov[3 * f0 + 2] + ov[3 * f1 + 2] + ov[3 * f2 + 2]) / 3.0f;
            g_obp[i] = make_float4(bx, by, bz, bx * bx + by * by + bz * bz);
            mnx = mxx = bx; mny = mxy = by; mnz = mxz = bz;
        }
#pragma unroll
        for (int o = 16; o > 0; o >>= 1) {
            mnx = fminf(mnx, __shfl_xor_sync(0xffffffffu, mnx, o));
            mny = fminf(mny, __shfl_xor_sync(0xffffffffu, mny, o));
            mnz = fminf(mnz, __shfl_xor_sync(0xffffffffu, mnz, o));
            mxx = fmaxf(mxx, __shfl_xor_sync(0xffffffffu, mxx, o));
            mxy = fmaxf(mxy, __shfl_xor_sync(0xffffffffu, mxy, o));
            mxz = fmaxf(mxz, __shfl_xor_sync(0xffffffffu, mxz, o));
        }
        if ((threadIdx.x & 31) == 0 && (blockIdx.x * 256 + (threadIdx.x & ~31)) < N_OF) {
            atomicMin(&g_bbox2[0], f2o(mnx));
            atomicMin(&g_bbox2[1], f2o(mny));
            atomicMin(&g_bbox2[2], f2o(mnz));
            atomicMax(&g_bbox2[3], f2o(mxx));
            atomicMax(&g_bbox2[4], f2o(mxy));
            atomicMax(&g_bbox2[5], f2o(mxz));
        }
    }
    if (i < N_SF) {
        int f0 = sf[3 * i], f1 = sf[3 * i + 1], f2 = sf[3 * i + 2];
        float bx = (sv[3 * f0] + sv[3 * f1] + sv[3 * f2]) / 3.0f;
        float by = (sv[3 * f0 + 1] + sv[3 * f1 + 1] + sv[3 * f2 + 1]) / 3.0f;
        float bz = (sv[3 * f0 + 2] + sv[3 * f1 + 2] + sv[3 * f2 + 2]) / 3.0f;
        g_sb[i] = make_float4(bx, by, bz, bx * bx + by * by + bz * bz);
    }
}

// ---------------- kernel C: sample gen + ALL cell counts ----------------
__global__ void gen_count_kernel(const float* __restrict__ ov,
                                 const float* __restrict__ sv,
                                 const int*   __restrict__ sf) {
    int j = blockIdx.x * 256 + threadIdx.x;

    if (j < N_SAMPLES) {
        U2 ua = threefry2x32(RK1.a, RK1.b, 0u, (uint32_t)j);
        U2 ub = threefry2x32(RK2.a, RK2.b, 0u, (uint32_t)j);

        float u1 = bits_to_uniform(ua.a ^ ua.b);
        float r2 = bits_to_uniform(ub.a ^ ub.b);
        float sq = sqrtf(u1);
        float a = 1.0f - sq;
        float b = sq * (1.0f - r2);
        float c = sq * r2;
        int f = j / NSAMP;
        int i0 = sf[3 * f], i1 = sf[3 * f + 1], i2 = sf[3 * f + 2];
        float x = a * sv[3 * i0]     + b * sv[3 * i1]     + c * sv[3 * i2];
        float y = a * sv[3 * i0 + 1] + b * sv[3 * i1 + 1] + c * sv[3 * i2 + 1];
        float z = a * sv[3 * i0 + 2] + b * sv[3 * i1 + 2] + c * sv[3 * i2 + 2];
        g_samples[j] = make_float4(x, y, z, x * x + y * y + z * z);

        GridGeom g = load_geom(g_bbox, GRID_G);
        int cx = cell_coord(x, g.x0, g.invh, GRID_G);
        int cy = cell_coord(y, g.y0, g.invh, GRID_G);
        int cz = cell_coord(z, g.z0, g.invh, GRID_G);
        atomicAdd(&g_count3[(cz * GRID_G + cy) * GRID_G + cx], 1);
    }
    if (j < N_OV) {
        GridGeom g = load_geom(g_bbox, GRID_G);
        int cx = cell_coord(ov[3 * j],     g.x0, g.invh, GRID_G);
        int cy = cell_coord(ov[3 * j + 1], g.y0, g.invh, GRID_G);
        int cz = cell_coord(ov[3 * j + 2], g.z0, g.invh, GRID_G);
        atomicAdd(&g_count[(cz * GRID_G + cy) * GRID_G + cx], 1);
    }
    if (j < N_OF) {
        GridGeom g = load_geom(g_bbox2, GRID_G2);
        float4 b = g_obp[j];
        int cx = cell_coord(b.x, g.x0, g.invh, GRID_G2);
        int cy = cell_coord(b.y, g.y0, g.invh, GRID_G2);
        int cz = cell_coord(b.z, g.z0, g.invh, GRID_G2);
        atomicAdd(&g_count2[(cz * GRID_G2 + cy) * GRID_G2 + cx], 1);
    }
}

// ---------------- scan helper ----------------
__device__ __forceinline__ void block_scan_1024(const int* __restrict__ cnt_arr,
                                                int* __restrict__ start_arr,
                                                int* __restrict__ bsum_arr,
                                                int seg_block) {
    __shared__ int sd[1024];
    int tid = threadIdx.x;
    int cell = seg_block * 1024 + tid;
    int cnt = cnt_arr[cell];
    sd[tid] = cnt;
    __syncthreads();
#pragma unroll
    for (int off = 1; off < 1024; off <<= 1) {
        int v = (tid >= off) ? sd[tid - off] : 0;
        __syncthreads();
        sd[tid] += v;
        __syncthreads();
    }
    start_arr[cell] = sd[tid] - cnt;
    if (tid == 1023) bsum_arr[seg_block] = sd[1023];
}

// ---------------- kernel D2: block-level scans (3 grids, 96 blocks) --------
__global__ void __launch_bounds__(1024) scan1_kernel() {
    int b = blockIdx.x;
    if (b < SCAN_BLOCKS) {
        block_scan_1024(g_count, g_cellstart, g_blocksum, b);
    } else if (b < SCAN_BLOCKS + SCAN_BLOCKS2) {
        block_scan_1024(g_count2, g_cellstart2, g_blocksum2, b - SCAN_BLOCKS);
    } else {
        block_scan_1024(g_count3, g_cellstart3, g_blocksum3, b - SCAN_BLOCKS - SCAN_BLOCKS2);
    }
}

// ---------------- kernel D3: scan of block sums (3 warps, one each) --------
__global__ void __launch_bounds__(96) scan2_kernel() {
    int tid = threadIdx.x;
    int w = tid >> 5, lane = tid & 31;
    const int* bsum;
    int* boff;
    int* last;
    if (w == 0)      { bsum = g_blocksum;  boff = g_blockoff;  last = &g_cellstart[NCELLS]; }
    else if (w == 1) { bsum = g_blocksum2; boff = g_blockoff2; last = &g_cellstart2[NCELLS2]; }
    else             { bsum = g_blocksum3; boff = g_blockoff3; last = &g_cellstart3[NCELLS]; }
    int v = bsum[lane];
    int s = v;
#pragma unroll
    for (int off = 1; off < 32; off <<= 1) {
        int t = __shfl_up_sync(0xffffffffu, s, off);
        if (lane >= off) s += t;
    }
    boff[lane] = s - v;
    if (lane == 31) *last = s;
}

// ---------------- kernel D4: add block offsets (3 grids) ----------------
__global__ void __launch_bounds__(1024) scan3_kernel() {
    int b = blockIdx.x;
    int tid = threadIdx.x;
    if (b < SCAN_BLOCKS) {
        g_cellstart[b * 1024 + tid] += g_blockoff[b];
    } else if (b < SCAN_BLOCKS + SCAN_BLOCKS2) {
        int bb = b - SCAN_BLOCKS;
        g_cellstart2[bb * 1024 + tid] += g_blockoff2[bb];
    } else {
        int bb = b - SCAN_BLOCKS - SCAN_BLOCKS2;
        g_cellstart3[bb * 1024 + tid] += g_blockoff3[bb];
    }
}

// ---------------- kernel D5: scatter (vertices, barycenters, samples) ------
__global__ void scatter_kernel(const float* __restrict__ ov,
                               const float* __restrict__ fp) {
    int i = blockIdx.x * 256 + threadIdx.x;
    if (i < N_OV) {
        GridGeom g = load_geom(g_bbox, GRID_G);
        float x = ov[3 * i], y = ov[3 * i + 1], z = ov[3 * i + 2];
        int cx = cell_coord(x, g.x0, g.invh, GRID_G);
        int cy = cell_coord(y, g.y0, g.invh, GRID_G);
        int cz = cell_coord(z, g.z0, g.invh, GRID_G);
        int c = (cz * GRID_G + cy) * GRID_G + cx;
        int pos = g_cellstart[c] + atomicAdd(&g_cursor[c], 1);
        g_sorted[pos] = make_float4(x, y, z, x * x + y * y + z * z);
    }
    if (i < N_OF) {
        GridGeom g = load_geom(g_bbox2, GRID_G2);
        float4 b = g_obp[i];
        int cx = cell_coord(b.x, g.x0, g.invh, GRID_G2);
        int cy = cell_coord(b.y, g.y0, g.invh, GRID_G2);
        int cz = cell_coord(b.z, g.z0, g.invh, GRID_G2);
        int c = (cz * GRID_G2 + cy) * GRID_G2 + cx;
        int pos = g_cellstart2[c] + atomicAdd(&g_cursor2[c], 1);
        g_sorted2[pos] = b;
    }
    if (i < N_SAMPLES) {
        GridGeom g = load_geom(g_bbox, GRID_G);
        float4 s = g_samples[i];
        int cx = cell_coord(s.x, g.x0, g.invh, GRID_G);
        int cy = cell_coord(s.y, g.y0, g.invh, GRID_G);
        int cz = cell_coord(s.z, g.z0, g.invh, GRID_G);
        int c = (cz * GRID_G + cy) * GRID_G + cx;
        int pos = g_cellstart3[c] + atomicAdd(&g_cursor3[c], 1);
        g_ssorted[pos] = s;
        g_sfp[pos] = fp[i / NSAMP];
    }
}

// ---------------- kernel E1: forward 1-NN, one WARP per query --------------
__global__ void __launch_bounds__(256) forward_warp_kernel() {
    int warp = (blockIdx.x * 256 + threadIdx.x) >> 5;
    int lane = threadIdx.x & 31;
    if (warp >= N_SF) return;

    GridGeom g = load_geom(g_bbox2, GRID_G2);
    float4 Q = g_sb[warp];
    float m2x = -2.0f * Q.x, m2y = -2.0f * Q.y, m2z = -2.0f * Q.z;
    int cx = cell_coord(Q.x, g.x0, g.invh, GRID_G2);
    int cy = cell_coord(Q.y, g.y0, g.invh, GRID_G2);
    int cz = cell_coord(Q.z, g.z0, g.invh, GRID_G2);
    const int G = GRID_G2;

    float best = 3.0e38f;
    for (int R = 0; R <= G; R++) {
        float bmin = best;
#pragma unroll
        for (int o = 16; o > 0; o >>= 1)
            bmin = fminf(bmin, __shfl_xor_sync(0xffffffffu, bmin, o));
        if (R > 0) {
            float lb = (float)(R - 1) * g.h;
            if (bmin + Q.w <= lb * lb) break;
        }
        int zlo = max(cz - R, 0), zhi = min(cz + R, G - 1);
        int ylo = max(cy - R, 0), yhi = min(cy + R, G - 1);
        int xlo = max(cx - R, 0), xhi = min(cx + R, G - 1);
        for (int z = zlo; z <= zhi; z++) {
            bool ze = (z == cz - R) || (z == cz + R);
            for (int y = ylo; y <= yhi; y++) {
                bool edge = ze || (y == cy - R) || (y == cy + R);
                int rowbase = (z * G + y) * G;
                if (edge) {
                    int p0 = __ldg(&g_cellstart2[rowbase + xlo]);
                    int p1 = __ldg(&g_cellstart2[rowbase + xhi + 1]);
                    for (int p = p0 + lane; p < p1; p += 32) {
                        float4 v = g_sorted2[p];
                        float t = fmaf(v.x, m2x, fmaf(v.y, m2y, fmaf(v.z, m2z, v.w)));
                        best = fminf(best, t);
                    }
                } else {
                    int xa = cx - R, xb = cx + R;
                    if (xa >= 0) {
                        int c0 = rowbase + xa;
                        int p0 = __ldg(&g_cellstart2[c0]), p1 = __ldg(&g_cellstart2[c0 + 1]);
                        for (int p = p0 + lane; p < p1; p += 32) {
                            float4 v = g_sorted2[p];
                            float t = fmaf(v.x, m2x, fmaf(v.y, m2y, fmaf(v.z, m2z, v.w)));
                            best = fminf(best, t);
                        }
                    }
                    if (xb <= G - 1) {
                        int c0 = rowbase + xb;
                        int p0 = __ldg(&g_cellstart2[c0]), p1 = __ldg(&g_cellstart2[c0 + 1]);
                        for (int p = p0 + lane; p < p1; p += 32) {
                            float4 v = g_sorted2[p];
                            float t = fmaf(v.x, m2x, fmaf(v.y, m2y, fmaf(v.z, m2z, v.w)));
                            best = fminf(best, t);
                        }
                    }
                }
            }
        }
        if (zlo == 0 && ylo == 0 && xlo == 0 &&
            zhi == G - 1 && yhi == G - 1 && xhi == G - 1) break;
    }
    float bmin = best;
#pragma unroll
    for (int o = 16; o > 0; o >>= 1)
        bmin = fminf(bmin, __shfl_xor_sync(0xffffffffu, bmin, o));
    if (lane == 0)
        g_minfwd[warp] = __float_as_uint(fmaxf(bmin + Q.w, 0.0f));
}

// ---------------- kernel E2: reverse 1-NN on cell-sorted samples -----------
__global__ void __launch_bounds__(256) reverse_sorted_kernel() {
    int j = blockIdx.x * 256 + threadIdx.x;

    float d = 0.0f;
    double contrib = 0.0;
    if (j < N_SAMPLES) {
        GridGeom g = load_geom(g_bbox, GRID_G);
        float4 s = g_ssorted[j];
        float d2 = shell_nn<GRID_G>(s.x, s.y, s.z, s.w, g, g_cellstart, g_sorted);
        d = sqrtf(d2);
        contrib = (double)(g_sfp[j] * d);
    }

    __shared__ double rsum[256];
    __shared__ float rmax[256];
    int tid = threadIdx.x;
    rsum[tid] = contrib;
    rmax[tid] = d;
    __syncthreads();
#pragma unroll
    for (int o = 128; o > 0; o >>= 1) {
        if (tid < o) {
            rsum[tid] += rsum[tid + o];
            rmax[tid] = fmaxf(rmax[tid], rmax[tid + o]);
        }
        __syncthreads();
    }
    if (tid == 0) {
        g_part[blockIdx.x] = rsum[0];
        atomicMax(&g_maxbits, __float_as_uint(rmax[0]));
    }
}

// ---------------- kernel F: final ----------------
__global__ void __launch_bounds__(512) final_kernel(const float* __restrict__ fp,
                                                    float* __restrict__ out) {
    __shared__ double red[512];
    int tid = threadIdx.x;

    double fwd = 0.0, pen = 0.0, rev = 0.0;
    for (int i = tid; i < N_SF; i += 512) {
        float p = fp[i];
        float d2 = __uint_as_float(g_minfwd[i]);
        fwd += (double)(p * sqrtf(d2));
        pen += (double)(1.0f - p);
    }
    for (int b = tid; b < REV_BLOCKS; b += 512) rev += g_part[b];

    double totF, totP, totR;
    red[tid] = fwd; __syncthreads();
    for (int o = 256; o > 0; o >>= 1) { if (tid < o) red[tid] += red[tid + o]; __syncthreads(); }
    totF = red[0]; __syncthreads();
    red[tid] = pen; __syncthreads();
    for (int o = 256; o > 0; o >>= 1) { if (tid < o) red[tid] += red[tid + o]; __syncthreads(); }
    totP = red[0]; __syncthreads();
    red[tid] = rev; __syncthreads();
    for (int o = 256; o > 0; o >>= 1) { if (tid < o) red[tid] += red[tid + o]; __syncthreads(); }
    totR = red[0];

    if (tid == 0) {
        double maxd = (double)__uint_as_float(g_maxbits);
        double result = totF + 1e-4 * totP + totR / (maxd + 1e-8) * 0.1;
        out[0] = (float)result;
    }
}

// ---------------- launch ----------------
extern "C" void kernel_launch(void* const* d_in, const int* in_sizes, int n_in,
                              void* d_out, int out_size) {
    const float* ov = (const float*)d_in[0];
    const int*   of = (const int*)  d_in[1];
    const float* sv = (const float*)d_in[2];
    const int*   sf = (const int*)  d_in[3];
    const float* fp = (const float*)d_in[4];
    float* out = (float*)d_out;

    init_prep_kernel<<<(NCELLS + 255) / 256, 256>>>(ov, of, sv, sf);
    gen_count_kernel<<<GEN_BLOCKS, 256>>>(ov, sv, sf);
    scan1_kernel<<<3 * SCAN_BLOCKS, 1024>>>();
    scan2_kernel<<<1, 96>>>();
    scan3_kernel<<<3 * SCAN_BLOCKS, 1024>>>();
    scatter_kernel<<<GEN_BLOCKS, 256>>>(ov, fp);

    forward_warp_kernel<<<FWD_WARP_BLOCKS, 256>>>();
    reverse_sorted_kernel<<<REV_BLOCKS, 256>>>();
    final_kernel<<<1, 512>>>(fp, out);
}

// round 11
// speedup vs baseline: 1.9341x; 1.1654x over previous
#include <cuda_runtime.h>
#include <cuda_bf16.h>
#include <stdint.h>

// ---------------- problem constants (static shapes) ----------------
#define N_OV 20000
#define N_OF 30000
#define N_SV 4000
#define N_SF 5000
#define NSAMP 50
#define N_SAMPLES 250000
// vertex grid (reverse term) — also used to sort samples
#define GRID_G 32
#define NCELLS (GRID_G * GRID_G * GRID_G)       // 32768
#define SCAN_BLOCKS 32
// barycenter grid (forward term)
#define GRID_G2 32
#define NCELLS2 (GRID_G2 * GRID_G2 * GRID_G2)   // 32768
#define SCAN_BLOCKS2 32
#define REV_BLOCKS 977                           // ceil(250000/256)
#define FWD_WARP_BLOCKS 625                      // 5000 warps
#define FUSED_BLOCKS (FWD_WARP_BLOCKS + REV_BLOCKS)
#define GEN_BLOCKS 977

// ---------------- device scratch (static, no runtime alloc) ----------------
__device__ float4    g_obp[N_OF];
__device__ float4    g_sb[N_SF];
__device__ unsigned  g_minfwd[N_SF];
__device__ float4    g_samples[N_SAMPLES];
__device__ float4    g_ssorted[N_SAMPLES];
__device__ float     g_sfp[N_SAMPLES];
__device__ unsigned  g_maxbits;
__device__ double    g_part[REV_BLOCKS];
__device__ unsigned  g_done;                    // fused-kernel completion counter
// grid V (vertices)
__device__ unsigned  g_bbox[6];
__device__ int       g_count[NCELLS];
__device__ int       g_cursor[NCELLS];
__device__ int       g_cellstart[NCELLS + 1];
__device__ int       g_blocksum[SCAN_BLOCKS];
__device__ float4    g_sorted[N_OV];
// grid B (original barycenters)
__device__ unsigned  g_bbox2[6];
__device__ int       g_count2[NCELLS2];
__device__ int       g_cursor2[NCELLS2];
__device__ int       g_cellstart2[NCELLS2 + 1];
__device__ int       g_blocksum2[SCAN_BLOCKS2];
__device__ float4    g_sorted2[N_OF];
// grid S (samples, same geometry as grid V)
__device__ int       g_count3[NCELLS];
__device__ int       g_cursor3[NCELLS];
__device__ int       g_cellstart3[NCELLS + 1];
__device__ int       g_blocksum3[SCAN_BLOCKS];

// ---------------- ordered-float helpers ----------------
__device__ __forceinline__ unsigned f2o(float f) {
    unsigned u = __float_as_uint(f);
    return (u & 0x80000000u) ? ~u : (u | 0x80000000u);
}
__device__ __forceinline__ float o2f(unsigned u) {
    u = (u & 0x80000000u) ? (u & 0x7fffffffu) : ~u;
    return __uint_as_float(u);
}

// ---------------- threefry2x32 (JAX partitionable, 20 rounds) ----------------
__host__ __device__ constexpr uint32_t rotl32(uint32_t x, int r) {
    return (x << r) | (x >> (32 - r));
}
struct U2 { uint32_t a, b; };
__host__ __device__ constexpr U2 threefry2x32(uint32_t k0, uint32_t k1,
                                              uint32_t x0, uint32_t x1) {
    uint32_t ks0 = k0, ks1 = k1, ks2 = k0 ^ k1 ^ 0x1BD11BDAu;
    x0 += ks0; x1 += ks1;
    x0 += x1; x1 = rotl32(x1, 13); x1 ^= x0;
    x0 += x1; x1 = rotl32(x1, 15); x1 ^= x0;
    x0 += x1; x1 = rotl32(x1, 26); x1 ^= x0;
    x0 += x1; x1 = rotl32(x1,  6); x1 ^= x0;
    x0 += ks1; x1 += ks2 + 1u;
    x0 += x1; x1 = rotl32(x1, 17); x1 ^= x0;
    x0 += x1; x1 = rotl32(x1, 29); x1 ^= x0;
    x0 += x1; x1 = rotl32(x1, 16); x1 ^= x0;
    x0 += x1; x1 = rotl32(x1, 24); x1 ^= x0;
    x0 += ks2; x1 += ks0 + 2u;
    x0 += x1; x1 = rotl32(x1, 13); x1 ^= x0;
    x0 += x1; x1 = rotl32(x1, 15); x1 ^= x0;
    x0 += x1; x1 = rotl32(x1, 26); x1 ^= x0;
    x0 += x1; x1 = rotl32(x1,  6); x1 ^= x0;
    x0 += ks0; x1 += ks1 + 3u;
    x0 += x1; x1 = rotl32(x1, 17); x1 ^= x0;
    x0 += x1; x1 = rotl32(x1, 29); x1 ^= x0;
    x0 += x1; x1 = rotl32(x1, 16); x1 ^= x0;
    x0 += x1; x1 = rotl32(x1, 24); x1 ^= x0;
    x0 += ks1; x1 += ks2 + 4u;
    x0 += x1; x1 = rotl32(x1, 13); x1 ^= x0;
    x0 += x1; x1 = rotl32(x1, 15); x1 ^= x0;
    x0 += x1; x1 = rotl32(x1, 26); x1 ^= x0;
    x0 += x1; x1 = rotl32(x1,  6); x1 ^= x0;
    x0 += ks2; x1 += ks0 + 5u;
    return {x0, x1};
}
constexpr U2 RK1 = threefry2x32(0u, 42u, 0u, 0u);
constexpr U2 RK2 = threefry2x32(0u, 42u, 0u, 1u);

__device__ __forceinline__ float bits_to_uniform(uint32_t bits) {
    return __uint_as_float((bits >> 9) | 0x3f800000u) - 1.0f;
}

// ---------------- grid geometry ----------------
struct GridGeom { float x0, y0, z0, invh, h; };
__device__ __forceinline__ GridGeom load_geom(const unsigned* bbox, int G) {
    GridGeom g;
    g.x0 = o2f(bbox[0]); g.y0 = o2f(bbox[1]); g.z0 = o2f(bbox[2]);
    float ex = o2f(bbox[3]) - g.x0;
    float ey = o2f(bbox[4]) - g.y0;
    float ez = o2f(bbox[5]) - g.z0;
    float e = fmaxf(fmaxf(ex, ey), fmaxf(ez, 1e-20f));
    g.h = e / (float)G;
    g.invh = (float)G / e;
    return g;
}
__device__ __forceinline__ int cell_coord(float v, float v0, float invh, int G) {
    int c = (int)((v - v0) * invh);
    return min(max(c, 0), G - 1);
}

// ---------------- exact 1-NN: fast 3^3 box, then expanding shells ----------
template <int G>
__device__ __forceinline__ float shell_nn(float qx, float qy, float qz, float qw,
                                          const GridGeom g,
                                          const int* __restrict__ cellstart,
                                          const float4* __restrict__ sorted) {
    float m2x = -2.0f * qx, m2y = -2.0f * qy, m2z = -2.0f * qz;
    int cx = cell_coord(qx, g.x0, g.invh, G);
    int cy = cell_coord(qy, g.y0, g.invh, G);
    int cz = cell_coord(qz, g.z0, g.invh, G);

    float best = 3.0e38f;

    // ---- fast path: full 3x3x3 box as 9 contiguous x-row segments ----
    {
        int zlo = max(cz - 1, 0), zhi = min(cz + 1, G - 1);
        int ylo = max(cy - 1, 0), yhi = min(cy + 1, G - 1);
        int xlo = max(cx - 1, 0), xhi = min(cx + 1, G - 1);
        for (int z = zlo; z <= zhi; z++) {
            for (int y = ylo; y <= yhi; y++) {
                int rowbase = (z * G + y) * G;
                int p0 = __ldg(&cellstart[rowbase + xlo]);
                int p1 = __ldg(&cellstart[rowbase + xhi + 1]);
                for (int p = p0; p < p1; p++) {
                    float4 v = sorted[p];
                    float t = fmaf(v.x, m2x, fmaf(v.y, m2y, fmaf(v.z, m2z, v.w)));
                    best = fminf(best, t);
                }
            }
        }
    }

    // ---- slow path: expanding shells R >= 2 ----
    for (int R = 2; R <= G; R++) {
        float lb = (float)(R - 1) * g.h;
        if (best + qw <= lb * lb) break;
        int zlo = max(cz - R, 0), zhi = min(cz + R, G - 1);
        int ylo = max(cy - R, 0), yhi = min(cy + R, G - 1);
        int xlo = max(cx - R, 0), xhi = min(cx + R, G - 1);
        for (int z = zlo; z <= zhi; z++) {
            bool ze = (z == cz - R) || (z == cz + R);
            for (int y = ylo; y <= yhi; y++) {
                bool edge = ze || (y == cy - R) || (y == cy + R);
                int rowbase = (z * G + y) * G;
                if (edge) {
                    int p0 = __ldg(&cellstart[rowbase + xlo]);
                    int p1 = __ldg(&cellstart[rowbase + xhi + 1]);
                    for (int p = p0; p < p1; p++) {
                        float4 v = sorted[p];
                        float t = fmaf(v.x, m2x, fmaf(v.y, m2y, fmaf(v.z, m2z, v.w)));
                        best = fminf(best, t);
                    }
                } else {
                    int xa = cx - R, xb = cx + R;
                    if (xa >= 0) {
                        int c0 = rowbase + xa;
                        int p0 = __ldg(&cellstart[c0]), p1 = __ldg(&cellstart[c0 + 1]);
                        for (int p = p0; p < p1; p++) {
                            float4 v = sorted[p];
                            float t = fmaf(v.x, m2x, fmaf(v.y, m2y, fmaf(v.z, m2z, v.w)));
                            best = fminf(best, t);
                        }
                    }
                    if (xb <= G - 1) {
                        int c0 = rowbase + xb;
                        int p0 = __ldg(&cellstart[c0]), p1 = __ldg(&cellstart[c0 + 1]);
                        for (int p = p0; p < p1; p++) {
                            float4 v = sorted[p];
                            float t = fmaf(v.x, m2x, fmaf(v.y, m2y, fmaf(v.z, m2z, v.w)));
                            best = fminf(best, t);
                        }
                    }
                }
            }
        }
        if (zlo == 0 && ylo == 0 && xlo == 0 &&
            zhi == G - 1 && yhi == G - 1 && xhi == G - 1) break;
    }
    return fmaxf(best + qw, 0.0f);
}

// ---------------- kernel A: fused init + prep ----------------
__global__ void init_prep_kernel(const float* __restrict__ ov,
                                 const int*   __restrict__ of,
                                 const float* __restrict__ sv,
                                 const int*   __restrict__ sf) {
    int i = blockIdx.x * 256 + threadIdx.x;
    if (i < NCELLS)  { g_count[i] = 0;  g_cursor[i] = 0;
                       g_count3[i] = 0; g_cursor3[i] = 0; }
    if (i < NCELLS2) { g_count2[i] = 0; g_cursor2[i] = 0; }
    if (i == 0) {
        g_maxbits = 0u;
        g_done = 0u;
        for (int k = 0; k < 3; k++) { g_bbox[k] = 0xFFFFFFFFu;  g_bbox[k + 3] = 0u; }
        for (int k = 0; k < 3; k++) { g_bbox2[k] = 0xFFFFFFFFu; g_bbox2[k + 3] = 0u; }
    }

    // bbox of original vertices
    {
        float mnx =  3.0e38f, mxx = -3.0e38f;
        float mny =  3.0e38f, mxy = -3.0e38f;
        float mnz =  3.0e38f, mxz = -3.0e38f;
        if (i < N_OV) {
            mnx = mxx = ov[3 * i];
            mny = mxy = ov[3 * i + 1];
            mnz = mxz = ov[3 * i + 2];
        }
#pragma unroll
        for (int o = 16; o > 0; o >>= 1) {
            mnx = fminf(mnx, __shfl_xor_sync(0xffffffffu, mnx, o));
            mny = fminf(mny, __shfl_xor_sync(0xffffffffu, mny, o));
            mnz = fminf(mnz, __shfl_xor_sync(0xffffffffu, mnz, o));
            mxx = fmaxf(mxx, __shfl_xor_sync(0xffffffffu, mxx, o));
            mxy = fmaxf(mxy, __shfl_xor_sync(0xffffffffu, mxy, o));
            mxz = fmaxf(mxz, __shfl_xor_sync(0xffffffffu, mxz, o));
        }
        if ((threadIdx.x & 31) == 0 && (blockIdx.x * 256 + (threadIdx.x & ~31)) < N_OV) {
            atomicMin(&g_bbox[0], f2o(mnx));
            atomicMin(&g_bbox[1], f2o(mny));
            atomicMin(&g_bbox[2], f2o(mnz));
            atomicMax(&g_bbox[3], f2o(mxx));
            atomicMax(&g_bbox[4], f2o(mxy));
            atomicMax(&g_bbox[5], f2o(mxz));
        }
    }
    // original barycenters + their bbox
    {
        float bx, by, bz;
        float mnx =  3.0e38f, mxx = -3.0e38f;
        float mny =  3.0e38f, mxy = -3.0e38f;
        float mnz =  3.0e38f, mxz = -3.0e38f;
        if (i < N_OF) {
            int f0 = of[3 * i], f1 = of[3 * i + 1], f2 = of[3 * i + 2];
            bx = (ov[3 * f0] + ov[3 * f1] + ov[3 * f2]) / 3.0f;
            by = (ov[3 * f0 + 1] + ov[3 * f1 + 1] + ov[3 * f2 + 1]) / 3.0f;
            bz = (ov[3 * f0 + 2] + ov[3 * f1 + 2] + ov[3 * f2 + 2]) / 3.0f;
            g_obp[i] = make_float4(bx, by, bz, bx * bx + by * by + bz * bz);
            mnx = mxx = bx; mny = mxy = by; mnz = mxz = bz;
        }
#pragma unroll
        for (int o = 16; o > 0; o >>= 1) {
            mnx = fminf(mnx, __shfl_xor_sync(0xffffffffu, mnx, o));
            mny = fminf(mny, __shfl_xor_sync(0xffffffffu, mny, o));
            mnz = fminf(mnz, __shfl_xor_sync(0xffffffffu, mnz, o));
            mxx = fmaxf(mxx, __shfl_xor_sync(0xffffffffu, mxx, o));
            mxy = fmaxf(mxy, __shfl_xor_sync(0xffffffffu, mxy, o));
            mxz = fmaxf(mxz, __shfl_xor_sync(0xffffffffu, mxz, o));
        }
        if ((threadIdx.x & 31) == 0 && (blockIdx.x * 256 + (threadIdx.x & ~31)) < N_OF) {
            atomicMin(&g_bbox2[0], f2o(mnx));
            atomicMin(&g_bbox2[1], f2o(mny));
            atomicMin(&g_bbox2[2], f2o(mnz));
            atomicMax(&g_bbox2[3], f2o(mxx));
            atomicMax(&g_bbox2[4], f2o(mxy));
            atomicMax(&g_bbox2[5], f2o(mxz));
        }
    }
    if (i < N_SF) {
        int f0 = sf[3 * i], f1 = sf[3 * i + 1], f2 = sf[3 * i + 2];
        float bx = (sv[3 * f0] + sv[3 * f1] + sv[3 * f2]) / 3.0f;
        float by = (sv[3 * f0 + 1] + sv[3 * f1 + 1] + sv[3 * f2 + 1]) / 3.0f;
        float bz = (sv[3 * f0 + 2] + sv[3 * f1 + 2] + sv[3 * f2 + 2]) / 3.0f;
        g_sb[i] = make_float4(bx, by, bz, bx * bx + by * by + bz * bz);
    }
}

// ---------------- kernel B: sample gen + ALL cell counts ----------------
__global__ void gen_count_kernel(const float* __restrict__ ov,
                                 const float* __restrict__ sv,
                                 const int*   __restrict__ sf) {
    int j = blockIdx.x * 256 + threadIdx.x;

    if (j < N_SAMPLES) {
        U2 ua = threefry2x32(RK1.a, RK1.b, 0u, (uint32_t)j);
        U2 ub = threefry2x32(RK2.a, RK2.b, 0u, (uint32_t)j);

        float u1 = bits_to_uniform(ua.a ^ ua.b);
        float r2 = bits_to_uniform(ub.a ^ ub.b);
        float sq = sqrtf(u1);
        float a = 1.0f - sq;
        float b = sq * (1.0f - r2);
        float c = sq * r2;
        int f = j / NSAMP;
        int i0 = sf[3 * f], i1 = sf[3 * f + 1], i2 = sf[3 * f + 2];
        float x = a * sv[3 * i0]     + b * sv[3 * i1]     + c * sv[3 * i2];
        float y = a * sv[3 * i0 + 1] + b * sv[3 * i1 + 1] + c * sv[3 * i2 + 1];
        float z = a * sv[3 * i0 + 2] + b * sv[3 * i1 + 2] + c * sv[3 * i2 + 2];
        g_samples[j] = make_float4(x, y, z, x * x + y * y + z * z);

        GridGeom g = load_geom(g_bbox, GRID_G);
        int cx = cell_coord(x, g.x0, g.invh, GRID_G);
        int cy = cell_coord(y, g.y0, g.invh, GRID_G);
        int cz = cell_coord(z, g.z0, g.invh, GRID_G);
        atomicAdd(&g_count3[(cz * GRID_G + cy) * GRID_G + cx], 1);
    }
    if (j < N_OV) {
        GridGeom g = load_geom(g_bbox, GRID_G);
        int cx = cell_coord(ov[3 * j],     g.x0, g.invh, GRID_G);
        int cy = cell_coord(ov[3 * j + 1], g.y0, g.invh, GRID_G);
        int cz = cell_coord(ov[3 * j + 2], g.z0, g.invh, GRID_G);
        atomicAdd(&g_count[(cz * GRID_G + cy) * GRID_G + cx], 1);
    }
    if (j < N_OF) {
        GridGeom g = load_geom(g_bbox2, GRID_G2);
        float4 b = g_obp[j];
        int cx = cell_coord(b.x, g.x0, g.invh, GRID_G2);
        int cy = cell_coord(b.y, g.y0, g.invh, GRID_G2);
        int cz = cell_coord(b.z, g.z0, g.invh, GRID_G2);
        atomicAdd(&g_count2[(cz * GRID_G2 + cy) * GRID_G2 + cx], 1);
    }
}

// ---------------- scan helpers ----------------
__device__ __forceinline__ void block_scan_1024(const int* __restrict__ cnt_arr,
                                                int* __restrict__ start_arr,
                                                int* __restrict__ bsum_arr,
                                                int seg_block) {
    __shared__ int sd[1024];
    int tid = threadIdx.x;
    int cell = seg_block * 1024 + tid;
    int cnt = cnt_arr[cell];
    sd[tid] = cnt;
    __syncthreads();
#pragma unroll
    for (int off = 1; off < 1024; off <<= 1) {
        int v = (tid >= off) ? sd[tid - off] : 0;
        __syncthreads();
        sd[tid] += v;
        __syncthreads();
    }
    start_arr[cell] = sd[tid] - cnt;
    if (tid == 1023) bsum_arr[seg_block] = sd[1023];
}

// ---------------- kernel C: block-level scans (3 grids, 96 blocks) ---------
__global__ void __launch_bounds__(1024) scan1_kernel() {
    int b = blockIdx.x;
    if (b < SCAN_BLOCKS) {
        block_scan_1024(g_count, g_cellstart, g_blocksum, b);
    } else if (b < SCAN_BLOCKS + SCAN_BLOCKS2) {
        block_scan_1024(g_count2, g_cellstart2, g_blocksum2, b - SCAN_BLOCKS);
    } else {
        block_scan_1024(g_count3, g_cellstart3, g_blocksum3, b - SCAN_BLOCKS - SCAN_BLOCKS2);
    }
}

// ---------------- kernel D: add offsets (inline top scan, 96 blocks) -------
__global__ void __launch_bounds__(1024) scan3_kernel() {
    int b = blockIdx.x;
    int tid = threadIdx.x;
    const int* bsum;
    int* cs;
    int bb;
    int total_idx;
    if (b < SCAN_BLOCKS)                      { bsum = g_blocksum;  cs = g_cellstart;  bb = b;                          total_idx = NCELLS; }
    else if (b < SCAN_BLOCKS + SCAN_BLOCKS2)  { bsum = g_blocksum2; cs = g_cellstart2; bb = b - SCAN_BLOCKS;            total_idx = NCELLS2; }
    else                                      { bsum = g_blocksum3; cs = g_cellstart3; bb = b - SCAN_BLOCKS - SCAN_BLOCKS2; total_idx = NCELLS; }

    __shared__ int s_off, s_tot;
    if (tid < 32) {
        int v = bsum[tid];
        int s = v;
#pragma unroll
        for (int off = 1; off < 32; off <<= 1) {
            int t = __shfl_up_sync(0xffffffffu, s, off);
            if (tid >= off) s += t;
        }
        if (tid == (unsigned)bb) s_off = s - v;
        if (tid == 31) s_tot = s;
    }
    __syncthreads();
    cs[bb * 1024 + tid] += s_off;
    if (bb == 31 && tid == 0) cs[total_idx] = s_tot;
}

// ---------------- kernel E: scatter (vertices, barycenters, samples) -------
__global__ void scatter_kernel(const float* __restrict__ ov,
                               const float* __restrict__ fp) {
    int i = blockIdx.x * 256 + threadIdx.x;
    if (i < N_OV) {
        GridGeom g = load_geom(g_bbox, GRID_G);
        float x = ov[3 * i], y = ov[3 * i + 1], z = ov[3 * i + 2];
        int cx = cell_coord(x, g.x0, g.invh, GRID_G);
        int cy = cell_coord(y, g.y0, g.invh, GRID_G);
        int cz = cell_coord(z, g.z0, g.invh, GRID_G);
        int c = (cz * GRID_G + cy) * GRID_G + cx;
        int pos = g_cellstart[c] + atomicAdd(&g_cursor[c], 1);
        g_sorted[pos] = make_float4(x, y, z, x * x + y * y + z * z);
    }
    if (i < N_OF) {
        GridGeom g = load_geom(g_bbox2, GRID_G2);
        float4 b = g_obp[i];
        int cx = cell_coord(b.x, g.x0, g.invh, GRID_G2);
        int cy = cell_coord(b.y, g.y0, g.invh, GRID_G2);
        int cz = cell_coord(b.z, g.z0, g.invh, GRID_G2);
        int c = (cz * GRID_G2 + cy) * GRID_G2 + cx;
        int pos = g_cellstart2[c] + atomicAdd(&g_cursor2[c], 1);
        g_sorted2[pos] = b;
    }
    if (i < N_SAMPLES) {
        GridGeom g = load_geom(g_bbox, GRID_G);
        float4 s = g_samples[i];
        int cx = cell_coord(s.x, g.x0, g.invh, GRID_G);
        int cy = cell_coord(s.y, g.y0, g.invh, GRID_G);
        int cz = cell_coord(s.z, g.z0, g.invh, GRID_G);
        int c = (cz * GRID_G + cy) * GRID_G + cx;
        int pos = g_cellstart3[c] + atomicAdd(&g_cursor3[c], 1);
        g_ssorted[pos] = s;
        g_sfp[pos] = fp[i / NSAMP];
    }
}

// ---------------- kernel F: fused forward + reverse + final ----------------
__global__ void __launch_bounds__(256) fused_nn_kernel(const float* __restrict__ fp,
                                                       float* __restrict__ out) {
    int b = blockIdx.x;
    int tid = threadIdx.x;

    if (b < FWD_WARP_BLOCKS) {
        // -------- forward: one warp per simplified barycenter --------
        int warp = (b * 256 + tid) >> 5;
        int lane = tid & 31;
        if (warp < N_SF) {
            GridGeom g = load_geom(g_bbox2, GRID_G2);
            float4 Q = g_sb[warp];
            float m2x = -2.0f * Q.x, m2y = -2.0f * Q.y, m2z = -2.0f * Q.z;
            int cx = cell_coord(Q.x, g.x0, g.invh, GRID_G2);
            int cy = cell_coord(Q.y, g.y0, g.invh, GRID_G2);
            int cz = cell_coord(Q.z, g.z0, g.invh, GRID_G2);
            const int G = GRID_G2;

            float best = 3.0e38f;
            for (int R = 0; R <= G; R++) {
                float bmin = best;
#pragma unroll
                for (int o = 16; o > 0; o >>= 1)
                    bmin = fminf(bmin, __shfl_xor_sync(0xffffffffu, bmin, o));
                if (R > 0) {
                    float lb = (float)(R - 1) * g.h;
                    if (bmin + Q.w <= lb * lb) break;
                }
                int zlo = max(cz - R, 0), zhi = min(cz + R, G - 1);
                int ylo = max(cy - R, 0), yhi = min(cy + R, G - 1);
                int xlo = max(cx - R, 0), xhi = min(cx + R, G - 1);
                for (int z = zlo; z <= zhi; z++) {
                    bool ze = (z == cz - R) || (z == cz + R);
                    for (int y = ylo; y <= yhi; y++) {
                        bool edge = ze || (y == cy - R) || (y == cy + R);
                        int rowbase = (z * G + y) * G;
                        if (edge) {
                            int p0 = __ldg(&g_cellstart2[rowbase + xlo]);
                            int p1 = __ldg(&g_cellstart2[rowbase + xhi + 1]);
                            for (int p = p0 + lane; p < p1; p += 32) {
                                float4 v = g_sorted2[p];
                                float t = fmaf(v.x, m2x, fmaf(v.y, m2y, fmaf(v.z, m2z, v.w)));
                                best = fminf(best, t);
                            }
                        } else {
                            int xa = cx - R, xb = cx + R;
                            if (xa >= 0) {
                                int c0 = rowbase + xa;
                                int p0 = __ldg(&g_cellstart2[c0]), p1 = __ldg(&g_cellstart2[c0 + 1]);
                                for (int p = p0 + lane; p < p1; p += 32) {
                                    float4 v = g_sorted2[p];
                                    float t = fmaf(v.x, m2x, fmaf(v.y, m2y, fmaf(v.z, m2z, v.w)));
                                    best = fminf(best, t);
                                }
                            }
                            if (xb <= G - 1) {
                                int c0 = rowbase + xb;
                                int p0 = __ldg(&g_cellstart2[c0]), p1 = __ldg(&g_cellstart2[c0 + 1]);
                                for (int p = p0 + lane; p < p1; p += 32) {
                                    float4 v = g_sorted2[p];
                                    float t = fmaf(v.x, m2x, fmaf(v.y, m2y, fmaf(v.z, m2z, v.w)));
                                    best = fminf(best, t);
                                }
                            }
                        }
                    }
                }
                if (zlo == 0 && ylo == 0 && xlo == 0 &&
                    zhi == G - 1 && yhi == G - 1 && xhi == G - 1) break;
            }
            float bmin = best;
#pragma unroll
            for (int o = 16; o > 0; o >>= 1)
                bmin = fminf(bmin, __shfl_xor_sync(0xffffffffu, bmin, o));
            if (lane == 0)
                g_minfwd[warp] = __float_as_uint(fmaxf(bmin + Q.w, 0.0f));
        }
    } else {
        // -------- reverse: one thread per cell-sorted sample --------
        int rb = b - FWD_WARP_BLOCKS;
        int j = rb * 256 + tid;

        float d = 0.0f;
        double contrib = 0.0;
        if (j < N_SAMPLES) {
            GridGeom g = load_geom(g_bbox, GRID_G);
            float4 s = g_ssorted[j];
            float d2 = shell_nn<GRID_G>(s.x, s.y, s.z, s.w, g, g_cellstart, g_sorted);
            d = sqrtf(d2);
            contrib = (double)(g_sfp[j] * d);
        }

        __shared__ double rsum[256];
        __shared__ float rmax[256];
        rsum[tid] = contrib;
        rmax[tid] = d;
        __syncthreads();
#pragma unroll
        for (int o = 128; o > 0; o >>= 1) {
            if (tid < o) {
                rsum[tid] += rsum[tid + o];
                rmax[tid] = fmaxf(rmax[tid], rmax[tid + o]);
            }
            __syncthreads();
        }
        if (tid == 0) {
            g_part[rb] = rsum[0];
            atomicMax(&g_maxbits, __float_as_uint(rmax[0]));
        }
    }

    // -------- completion: last block runs the final reduction --------
    __syncthreads();
    __threadfence();
    __shared__ unsigned s_rank;
    if (tid == 0) s_rank = atomicAdd(&g_done, 1u);
    __syncthreads();
    if (s_rank != FUSED_BLOCKS - 1) return;

    // final reduction (deterministic: fixed loop order, double accumulation)
    __shared__ double red[256];
    double fwd = 0.0, pen = 0.0, rev = 0.0;
    for (int i = tid; i < N_SF; i += 256) {
        float p = fp[i];
        float d2 = __uint_as_float(g_minfwd[i]);
        fwd += (double)(p * sqrtf(d2));
        pen += (double)(1.0f - p);
    }
    for (int k = tid; k < REV_BLOCKS; k += 256) rev += g_part[k];

    double totF, totP, totR;
    red[tid] = fwd; __syncthreads();
#pragma unroll
    for (int o = 128; o > 0; o >>= 1) { if (tid < o) red[tid] += red[tid + o]; __syncthreads(); }
    totF = red[0]; __syncthreads();
    red[tid] = pen; __syncthreads();
#pragma unroll
    for (int o = 128; o > 0; o >>= 1) { if (tid < o) red[tid] += red[tid + o]; __syncthreads(); }
    totP = red[0]; __syncthreads();
    red[tid] = rev; __syncthreads();
#pragma unroll
    for (int o = 128; o > 0; o >>= 1) { if (tid < o) red[tid] += red[tid + o]; __syncthreads(); }
    totR = red[0];

    if (tid == 0) {
        double maxd = (double)__uint_as_float(g_maxbits);
        double result = totF + 1e-4 * totP + totR / (maxd + 1e-8) * 0.1;
        out[0] = (float)result;
    }
}

// ---------------- launch ----------------
extern "C" void kernel_launch(void* const* d_in, const int* in_sizes, int n_in,
                              void* d_out, int out_size) {
    const float* ov = (const float*)d_in[0];
    const int*   of = (const int*)  d_in[1];
    const float* sv = (const float*)d_in[2];
    const int*   sf = (const int*)  d_in[3];
    const float* fp = (const float*)d_in[4];
    float* out = (float*)d_out;

    init_prep_kernel<<<(NCELLS + 255) / 256, 256>>>(ov, of, sv, sf);
    gen_count_kernel<<<GEN_BLOCKS, 256>>>(ov, sv, sf);
    scan1_kernel<<<3 * SCAN_BLOCKS, 1024>>>();
    scan3_kernel<<<3 * SCAN_BLOCKS, 1024>>>();
    scatter_kernel<<<GEN_BLOCKS, 256>>>(ov, fp);
    fused_nn_kernel<<<FUSED_BLOCKS, 256>>>(fp, out);
}

// round 12
// speedup vs baseline: 1.9424x; 1.0043x over previous
#include <cuda_runtime.h>
#include <cuda_bf16.h>
#include <stdint.h>

// ---------------- problem constants (static shapes) ----------------
#define N_OV 20000
#define N_OF 30000
#define N_SV 4000
#define N_SF 5000
#define NSAMP 50
#define N_SAMPLES 250000
// vertex grid (reverse term) — also used to sort samples
#define GRID_G 32
#define NCELLS (GRID_G * GRID_G * GRID_G)       // 32768
#define SCAN_BLOCKS 32
// barycenter grid (forward term)
#define GRID_G2 32
#define NCELLS2 (GRID_G2 * GRID_G2 * GRID_G2)   // 32768
#define SCAN_BLOCKS2 32
#define REV_BLOCKS 977                           // ceil(250000/256)
#define FWD_WARP_BLOCKS 625                      // 5000 warps
#define FUSED_BLOCKS (FWD_WARP_BLOCKS + REV_BLOCKS)
#define GEN_BLOCKS 977

// ---------------- device scratch (static, no runtime alloc) ----------------
__device__ float4    g_obp[N_OF];
__device__ float4    g_sb[N_SF];
__device__ unsigned  g_minfwd[N_SF];
__device__ float4    g_samples[N_SAMPLES];
__device__ float4    g_ssorted[N_SAMPLES];
__device__ float     g_sfp[N_SAMPLES];
__device__ unsigned  g_maxbits;
__device__ double    g_part[REV_BLOCKS];
__device__ unsigned  g_done;
// grid V (vertices)
__device__ unsigned  g_bbox[6];
__device__ int       g_count[NCELLS];
__device__ int       g_cursor[NCELLS];
__device__ int       g_cellstart[NCELLS + 1];
__device__ int       g_blocksum[SCAN_BLOCKS];
__device__ float4    g_sorted[N_OV];
// grid B (original barycenters)
__device__ unsigned  g_bbox2[6];
__device__ int       g_count2[NCELLS2];
__device__ int       g_cursor2[NCELLS2];
__device__ int       g_cellstart2[NCELLS2 + 1];
__device__ int       g_blocksum2[SCAN_BLOCKS2];
__device__ float4    g_sorted2[N_OF];
// grid S (samples, same geometry as grid V)
__device__ int       g_count3[NCELLS];
__device__ int       g_cursor3[NCELLS];
__device__ int       g_cellstart3[NCELLS + 1];
__device__ int       g_blocksum3[SCAN_BLOCKS];

// ---------------- ordered-float helpers ----------------
__device__ __forceinline__ unsigned f2o(float f) {
    unsigned u = __float_as_uint(f);
    return (u & 0x80000000u) ? ~u : (u | 0x80000000u);
}
__device__ __forceinline__ float o2f(unsigned u) {
    u = (u & 0x80000000u) ? (u & 0x7fffffffu) : ~u;
    return __uint_as_float(u);
}

// ---------------- threefry2x32 (JAX partitionable, 20 rounds) ----------------
__host__ __device__ constexpr uint32_t rotl32(uint32_t x, int r) {
    return (x << r) | (x >> (32 - r));
}
struct U2 { uint32_t a, b; };
__host__ __device__ constexpr U2 threefry2x32(uint32_t k0, uint32_t k1,
                                              uint32_t x0, uint32_t x1) {
    uint32_t ks0 = k0, ks1 = k1, ks2 = k0 ^ k1 ^ 0x1BD11BDAu;
    x0 += ks0; x1 += ks1;
    x0 += x1; x1 = rotl32(x1, 13); x1 ^= x0;
    x0 += x1; x1 = rotl32(x1, 15); x1 ^= x0;
    x0 += x1; x1 = rotl32(x1, 26); x1 ^= x0;
    x0 += x1; x1 = rotl32(x1,  6); x1 ^= x0;
    x0 += ks1; x1 += ks2 + 1u;
    x0 += x1; x1 = rotl32(x1, 17); x1 ^= x0;
    x0 += x1; x1 = rotl32(x1, 29); x1 ^= x0;
    x0 += x1; x1 = rotl32(x1, 16); x1 ^= x0;
    x0 += x1; x1 = rotl32(x1, 24); x1 ^= x0;
    x0 += ks2; x1 += ks0 + 2u;
    x0 += x1; x1 = rotl32(x1, 13); x1 ^= x0;
    x0 += x1; x1 = rotl32(x1, 15); x1 ^= x0;
    x0 += x1; x1 = rotl32(x1, 26); x1 ^= x0;
    x0 += x1; x1 = rotl32(x1,  6); x1 ^= x0;
    x0 += ks0; x1 += ks1 + 3u;
    x0 += x1; x1 = rotl32(x1, 17); x1 ^= x0;
    x0 += x1; x1 = rotl32(x1, 29); x1 ^= x0;
    x0 += x1; x1 = rotl32(x1, 16); x1 ^= x0;
    x0 += x1; x1 = rotl32(x1, 24); x1 ^= x0;
    x0 += ks1; x1 += ks2 + 4u;
    x0 += x1; x1 = rotl32(x1, 13); x1 ^= x0;
    x0 += x1; x1 = rotl32(x1, 15); x1 ^= x0;
    x0 += x1; x1 = rotl32(x1, 26); x1 ^= x0;
    x0 += x1; x1 = rotl32(x1,  6); x1 ^= x0;
    x0 += ks2; x1 += ks0 + 5u;
    return {x0, x1};
}
constexpr U2 RK1 = threefry2x32(0u, 42u, 0u, 0u);
constexpr U2 RK2 = threefry2x32(0u, 42u, 0u, 1u);

__device__ __forceinline__ float bits_to_uniform(uint32_t bits) {
    return __uint_as_float((bits >> 9) | 0x3f800000u) - 1.0f;
}

// ---------------- grid geometry ----------------
struct GridGeom { float x0, y0, z0, invh, h; };
__device__ __forceinline__ GridGeom load_geom(const unsigned* bbox, int G) {
    GridGeom g;
    g.x0 = o2f(bbox[0]); g.y0 = o2f(bbox[1]); g.z0 = o2f(bbox[2]);
    float ex = o2f(bbox[3]) - g.x0;
    float ey = o2f(bbox[4]) - g.y0;
    float ez = o2f(bbox[5]) - g.z0;
    float e = fmaxf(fmaxf(ex, ey), fmaxf(ez, 1e-20f));
    g.h = e / (float)G;
    g.invh = (float)G / e;
    return g;
}
__device__ __forceinline__ int cell_coord(float v, float v0, float invh, int G) {
    int c = (int)((v - v0) * invh);
    return min(max(c, 0), G - 1);
}

// ---------------- full 3^3 box + expanding-shell search (slow path) --------
template <int G>
__device__ __forceinline__ float full_search(float qx, float qy, float qz, float qw,
                                             float m2x, float m2y, float m2z,
                                             int cx, int cy, int cz,
                                             const GridGeom g,
                                             const int* __restrict__ cellstart,
                                             const float4* __restrict__ sorted) {
    float best = 3.0e38f;
    // 3x3x3 box as 9 row segments
    {
        int zlo = max(cz - 1, 0), zhi = min(cz + 1, G - 1);
        int ylo = max(cy - 1, 0), yhi = min(cy + 1, G - 1);
        int xlo = max(cx - 1, 0), xhi = min(cx + 1, G - 1);
        for (int z = zlo; z <= zhi; z++) {
            for (int y = ylo; y <= yhi; y++) {
                int rowbase = (z * G + y) * G;
                int p0 = __ldg(&cellstart[rowbase + xlo]);
                int p1 = __ldg(&cellstart[rowbase + xhi + 1]);
                for (int p = p0; p < p1; p++) {
                    float4 v = sorted[p];
                    float t = fmaf(v.x, m2x, fmaf(v.y, m2y, fmaf(v.z, m2z, v.w)));
                    best = fminf(best, t);
                }
            }
        }
    }
    // shells R >= 2
    for (int R = 2; R <= G; R++) {
        float lb = (float)(R - 1) * g.h;
        if (best + qw <= lb * lb) break;
        int zlo = max(cz - R, 0), zhi = min(cz + R, G - 1);
        int ylo = max(cy - R, 0), yhi = min(cy + R, G - 1);
        int xlo = max(cx - R, 0), xhi = min(cx + R, G - 1);
        for (int z = zlo; z <= zhi; z++) {
            bool ze = (z == cz - R) || (z == cz + R);
            for (int y = ylo; y <= yhi; y++) {
                bool edge = ze || (y == cy - R) || (y == cy + R);
                int rowbase = (z * G + y) * G;
                if (edge) {
                    int p0 = __ldg(&cellstart[rowbase + xlo]);
                    int p1 = __ldg(&cellstart[rowbase + xhi + 1]);
                    for (int p = p0; p < p1; p++) {
                        float4 v = sorted[p];
                        float t = fmaf(v.x, m2x, fmaf(v.y, m2y, fmaf(v.z, m2z, v.w)));
                        best = fminf(best, t);
                    }
                } else {
                    int xa = cx - R, xb = cx + R;
                    if (xa >= 0) {
                        int c0 = rowbase + xa;
                        int p0 = __ldg(&cellstart[c0]), p1 = __ldg(&cellstart[c0 + 1]);
                        for (int p = p0; p < p1; p++) {
                            float4 v = sorted[p];
                            float t = fmaf(v.x, m2x, fmaf(v.y, m2y, fmaf(v.z, m2z, v.w)));
                            best = fminf(best, t);
                        }
                    }
                    if (xb <= G - 1) {
                        int c0 = rowbase + xb;
                        int p0 = __ldg(&cellstart[c0]), p1 = __ldg(&cellstart[c0 + 1]);
                        for (int p = p0; p < p1; p++) {
                            float4 v = sorted[p];
                            float t = fmaf(v.x, m2x, fmaf(v.y, m2y, fmaf(v.z, m2z, v.w)));
                            best = fminf(best, t);
                        }
                    }
                }
            }
        }
        if (zlo == 0 && ylo == 0 && xlo == 0 &&
            zhi == G - 1 && yhi == G - 1 && xhi == G - 1) break;
    }
    return best;
}

// ---------------- exact 1-NN: 2x2x2 fast box, certified fallback -----------
template <int G>
__device__ __forceinline__ float shell_nn(float qx, float qy, float qz, float qw,
                                          const GridGeom g,
                                          const int* __restrict__ cellstart,
                                          const float4* __restrict__ sorted) {
    float m2x = -2.0f * qx, m2y = -2.0f * qy, m2z = -2.0f * qz;
    float fx = (qx - g.x0) * g.invh;
    float fy = (qy - g.y0) * g.invh;
    float fz = (qz - g.z0) * g.invh;
    int cx = min(max((int)fx, 0), G - 1);
    int cy = min(max((int)fy, 0), G - 1);
    int cz = min(max((int)fz, 0), G - 1);

    // choose 2-cell span per dim toward the nearer side
    int bx = ((fx - (float)cx) >= 0.5f) ? cx : cx - 1;
    int by = ((fy - (float)cy) >= 0.5f) ? cy : cy - 1;
    int bz = ((fz - (float)cz) >= 0.5f) ? cz : cz - 1;
    int xlo = max(bx, 0), xhi = min(bx + 1, G - 1);
    int ylo = max(by, 0), yhi = min(by + 1, G - 1);
    int zlo = max(bz, 0), zhi = min(bz + 1, G - 1);

    // certified coverage radius: distance to nearest interior box face
    // (domain-edge faces cover infinitely — no points beyond them)
    float cov = 3.0e38f;
    if (xlo > 0)     cov = fminf(cov, qx - (g.x0 + (float)xlo * g.h));
    if (xhi < G - 1) cov = fminf(cov, (g.x0 + (float)(xhi + 1) * g.h) - qx);
    if (ylo > 0)     cov = fminf(cov, qy - (g.y0 + (float)ylo * g.h));
    if (yhi < G - 1) cov = fminf(cov, (g.y0 + (float)(yhi + 1) * g.h) - qy);
    if (zlo > 0)     cov = fminf(cov, qz - (g.z0 + (float)zlo * g.h));
    if (zhi < G - 1) cov = fminf(cov, (g.z0 + (float)(zhi + 1) * g.h) - qz);
    cov = fmaxf(cov, 0.0f) * 0.99999f;   // fp-safety margin

    // scan 8 cells as 4 contiguous row segments
    float best = 3.0e38f;
    for (int z = zlo; z <= zhi; z++) {
        for (int y = ylo; y <= yhi; y++) {
            int rowbase = (z * G + y) * G;
            int p0 = __ldg(&cellstart[rowbase + xlo]);
            int p1 = __ldg(&cellstart[rowbase + xhi + 1]);
            for (int p = p0; p < p1; p++) {
                float4 v = sorted[p];
                float t = fmaf(v.x, m2x, fmaf(v.y, m2y, fmaf(v.z, m2z, v.w)));
                best = fminf(best, t);
            }
        }
    }
    if (best + qw <= cov * cov)
        return fmaxf(best + qw, 0.0f);

    // fallback: full certified search (re-evals only re-min)
    best = fminf(best, full_search<G>(qx, qy, qz, qw, m2x, m2y, m2z,
                                      cx, cy, cz, g, cellstart, sorted));
    return fmaxf(best + qw, 0.0f);
}

// ---------------- kernel A: fused init + prep ----------------
__global__ void init_prep_kernel(const float* __restrict__ ov,
                                 const int*   __restrict__ of,
                                 const float* __restrict__ sv,
                                 const int*   __restrict__ sf) {
    int i = blockIdx.x * 256 + threadIdx.x;
    if (i < NCELLS)  { g_count[i] = 0;  g_cursor[i] = 0;
                       g_count3[i] = 0; g_cursor3[i] = 0; }
    if (i < NCELLS2) { g_count2[i] = 0; g_cursor2[i] = 0; }
    if (i == 0) {
        g_maxbits = 0u;
        g_done = 0u;
        for (int k = 0; k < 3; k++) { g_bbox[k] = 0xFFFFFFFFu;  g_bbox[k + 3] = 0u; }
        for (int k = 0; k < 3; k++) { g_bbox2[k] = 0xFFFFFFFFu; g_bbox2[k + 3] = 0u; }
    }

    // bbox of original vertices
    {
        float mnx =  3.0e38f, mxx = -3.0e38f;
        float mny =  3.0e38f, mxy = -3.0e38f;
        float mnz =  3.0e38f, mxz = -3.0e38f;
        if (i < N_OV) {
            mnx = mxx = ov[3 * i];
            mny = mxy = ov[3 * i + 1];
            mnz = mxz = ov[3 * i + 2];
        }
#pragma unroll
        for (int o = 16; o > 0; o >>= 1) {
            mnx = fminf(mnx, __shfl_xor_sync(0xffffffffu, mnx, o));
            mny = fminf(mny, __shfl_xor_sync(0xffffffffu, mny, o));
            mnz = fminf(mnz, __shfl_xor_sync(0xffffffffu, mnz, o));
            mxx = fmaxf(mxx, __shfl_xor_sync(0xffffffffu, mxx, o));
            mxy = fmaxf(mxy, __shfl_xor_sync(0xffffffffu, mxy, o));
            mxz = fmaxf(mxz, __shfl_xor_sync(0xffffffffu, mxz, o));
        }
        if ((threadIdx.x & 31) == 0 && (blockIdx.x * 256 + (threadIdx.x & ~31)) < N_OV) {
            atomicMin(&g_bbox[0], f2o(mnx));
            atomicMin(&g_bbox[1], f2o(mny));
            atomicMin(&g_bbox[2], f2o(mnz));
            atomicMax(&g_bbox[3], f2o(mxx));
            atomicMax(&g_bbox[4], f2o(mxy));
            atomicMax(&g_bbox[5], f2o(mxz));
        }
    }
    // original barycenters + their bbox
    {
        float bx, by, bz;
        float mnx =  3.0e38f, mxx = -3.0e38f;
        float mny =  3.0e38f, mxy = -3.0e38f;
        float mnz =  3.0e38f, mxz = -3.0e38f;
        if (i < N_OF) {
            int f0 = of[3 * i], f1 = of[3 * i + 1], f2 = of[3 * i + 2];
            bx = (ov[3 * f0] + ov[3 * f1] + ov[3 * f2]) / 3.0f;
            by = (ov[3 * f0 + 1] + ov[3 * f1 + 1] + ov[3 * f2 + 1]) / 3.0f;
            bz = (ov[3 * f0 + 2] + ov[3 * f1 + 2] + ov[3 * f2 + 2]) / 3.0f;
            g_obp[i] = make_float4(bx, by, bz, bx * bx + by * by + bz * bz);
            mnx = mxx = bx; mny = mxy = by; mnz = mxz = bz;
        }
#pragma unroll
        for (int o = 16; o > 0; o >>= 1) {
            mnx = fminf(mnx, __shfl_xor_sync(0xffffffffu, mnx, o));
            mny = fminf(mny, __shfl_xor_sync(0xffffffffu, mny, o));
            mnz = fminf(mnz, __shfl_xor_sync(0xffffffffu, mnz, o));
            mxx = fmaxf(mxx, __shfl_xor_sync(0xffffffffu, mxx, o));
            mxy = fmaxf(mxy, __shfl_xor_sync(0xffffffffu, mxy, o));
            mxz = fmaxf(mxz, __shfl_xor_sync(0xffffffffu, mxz, o));
        }
        if ((threadIdx.x & 31) == 0 && (blockIdx.x * 256 + (threadIdx.x & ~31)) < N_OF) {
            atomicMin(&g_bbox2[0], f2o(mnx));
            atomicMin(&g_bbox2[1], f2o(mny));
            atomicMin(&g_bbox2[2], f2o(mnz));
            atomicMax(&g_bbox2[3], f2o(mxx));
            atomicMax(&g_bbox2[4], f2o(mxy));
            atomicMax(&g_bbox2[5], f2o(mxz));
        }
    }
    if (i < N_SF) {
        int f0 = sf[3 * i], f1 = sf[3 * i + 1], f2 = sf[3 * i + 2];
        float bx = (sv[3 * f0] + sv[3 * f1] + sv[3 * f2]) / 3.0f;
        float by = (sv[3 * f0 + 1] + sv[3 * f1 + 1] + sv[3 * f2 + 1]) / 3.0f;
        float bz = (sv[3 * f0 + 2] + sv[3 * f1 + 2] + sv[3 * f2 + 2]) / 3.0f;
        g_sb[i] = make_float4(bx, by, bz, bx * bx + by * by + bz * bz);
    }
}

// ---------------- kernel B: sample gen + ALL cell counts ----------------
__global__ void gen_count_kernel(const float* __restrict__ ov,
                                 const float* __restrict__ sv,
                                 const int*   __restrict__ sf) {
    int j = blockIdx.x * 256 + threadIdx.x;

    if (j < N_SAMPLES) {
        U2 ua = threefry2x32(RK1.a, RK1.b, 0u, (uint32_t)j);
        U2 ub = threefry2x32(RK2.a, RK2.b, 0u, (uint32_t)j);

        float u1 = bits_to_uniform(ua.a ^ ua.b);
        float r2 = bits_to_uniform(ub.a ^ ub.b);
        float sq = sqrtf(u1);
        float a = 1.0f - sq;
        float b = sq * (1.0f - r2);
        float c = sq * r2;
        int f = j / NSAMP;
        int i0 = sf[3 * f], i1 = sf[3 * f + 1], i2 = sf[3 * f + 2];
        float x = a * sv[3 * i0]     + b * sv[3 * i1]     + c * sv[3 * i2];
        float y = a * sv[3 * i0 + 1] + b * sv[3 * i1 + 1] + c * sv[3 * i2 + 1];
        float z = a * sv[3 * i0 + 2] + b * sv[3 * i1 + 2] + c * sv[3 * i2 + 2];
        g_samples[j] = make_float4(x, y, z, x * x + y * y + z * z);

        GridGeom g = load_geom(g_bbox, GRID_G);
        int cx = cell_coord(x, g.x0, g.invh, GRID_G);
        int cy = cell_coord(y, g.y0, g.invh, GRID_G);
        int cz = cell_coord(z, g.z0, g.invh, GRID_G);
        atomicAdd(&g_count3[(cz * GRID_G + cy) * GRID_G + cx], 1);
    }
    if (j < N_OV) {
        GridGeom g = load_geom(g_bbox, GRID_G);
        int cx = cell_coord(ov[3 * j],     g.x0, g.invh, GRID_G);
        int cy = cell_coord(ov[3 * j + 1], g.y0, g.invh, GRID_G);
        int cz = cell_coord(ov[3 * j + 2], g.z0, g.invh, GRID_G);
        atomicAdd(&g_count[(cz * GRID_G + cy) * GRID_G + cx], 1);
    }
    if (j < N_OF) {
        GridGeom g = load_geom(g_bbox2, GRID_G2);
        float4 b = g_obp[j];
        int cx = cell_coord(b.x, g.x0, g.invh, GRID_G2);
        int cy = cell_coord(b.y, g.y0, g.invh, GRID_G2);
        int cz = cell_coord(b.z, g.z0, g.invh, GRID_G2);
        atomicAdd(&g_count2[(cz * GRID_G2 + cy) * GRID_G2 + cx], 1);
    }
}

// ---------------- scan helpers ----------------
__device__ __forceinline__ void block_scan_1024(const int* __restrict__ cnt_arr,
                                                int* __restrict__ start_arr,
                                                int* __restrict__ bsum_arr,
                                                int seg_block) {
    __shared__ int sd[1024];
    int tid = threadIdx.x;
    int cell = seg_block * 1024 + tid;
    int cnt = cnt_arr[cell];
    sd[tid] = cnt;
    __syncthreads();
#pragma unroll
    for (int off = 1; off < 1024; off <<= 1) {
        int v = (tid >= off) ? sd[tid - off] : 0;
        __syncthreads();
        sd[tid] += v;
        __syncthreads();
    }
    start_arr[cell] = sd[tid] - cnt;
    if (tid == 1023) bsum_arr[seg_block] = sd[1023];
}

// ---------------- kernel C: block-level scans (3 grids, 96 blocks) ---------
__global__ void __launch_bounds__(1024) scan1_kernel() {
    int b = blockIdx.x;
    if (b < SCAN_BLOCKS) {
        block_scan_1024(g_count, g_cellstart, g_blocksum, b);
    } else if (b < SCAN_BLOCKS + SCAN_BLOCKS2) {
        block_scan_1024(g_count2, g_cellstart2, g_blocksum2, b - SCAN_BLOCKS);
    } else {
        block_scan_1024(g_count3, g_cellstart3, g_blocksum3, b - SCAN_BLOCKS - SCAN_BLOCKS2);
    }
}

// ---------------- kernel D: add offsets (inline top scan, 96 blocks) -------
__global__ void __launch_bounds__(1024) scan3_kernel() {
    int b = blockIdx.x;
    int tid = threadIdx.x;
    const int* bsum;
    int* cs;
    int bb;
    int total_idx;
    if (b < SCAN_BLOCKS)                      { bsum = g_blocksum;  cs = g_cellstart;  bb = b;                          total_idx = NCELLS; }
    else if (b < SCAN_BLOCKS + SCAN_BLOCKS2)  { bsum = g_blocksum2; cs = g_cellstart2; bb = b - SCAN_BLOCKS;            total_idx = NCELLS2; }
    else                                      { bsum = g_blocksum3; cs = g_cellstart3; bb = b - SCAN_BLOCKS - SCAN_BLOCKS2; total_idx = NCELLS; }

    __shared__ int s_off, s_tot;
    if (tid < 32) {
        int v = bsum[tid];
        int s = v;
#pragma unroll
        for (int off = 1; off < 32; off <<= 1) {
            int t = __shfl_up_sync(0xffffffffu, s, off);
            if (tid >= off) s += t;
        }
        if (tid == (unsigned)bb) s_off = s - v;
        if (tid == 31) s_tot = s;
    }
    __syncthreads();
    cs[bb * 1024 + tid] += s_off;
    if (bb == 31 && tid == 0) cs[total_idx] = s_tot;
}

// ---------------- kernel E: scatter (vertices, barycenters, samples) -------
__global__ void scatter_kernel(const float* __restrict__ ov,
                               const float* __restrict__ fp) {
    int i = blockIdx.x * 256 + threadIdx.x;
    if (i < N_OV) {
        GridGeom g = load_geom(g_bbox, GRID_G);
        float x = ov[3 * i], y = ov[3 * i + 1], z = ov[3 * i + 2];
        int cx = cell_coord(x, g.x0, g.invh, GRID_G);
        int cy = cell_coord(y, g.y0, g.invh, GRID_G);
        int cz = cell_coord(z, g.z0, g.invh, GRID_G);
        int c = (cz * GRID_G + cy) * GRID_G + cx;
        int pos = g_cellstart[c] + atomicAdd(&g_cursor[c], 1);
        g_sorted[pos] = make_float4(x, y, z, x * x + y * y + z * z);
    }
    if (i < N_OF) {
        GridGeom g = load_geom(g_bbox2, GRID_G2);
        float4 b = g_obp[i];
        int cx = cell_coord(b.x, g.x0, g.invh, GRID_G2);
        int cy = cell_coord(b.y, g.y0, g.invh, GRID_G2);
        int cz = cell_coord(b.z, g.z0, g.invh, GRID_G2);
        int c = (cz * GRID_G2 + cy) * GRID_G2 + cx;
        int pos = g_cellstart2[c] + atomicAdd(&g_cursor2[c], 1);
        g_sorted2[pos] = b;
    }
    if (i < N_SAMPLES) {
        GridGeom g = load_geom(g_bbox, GRID_G);
        float4 s = g_samples[i];
        int cx = cell_coord(s.x, g.x0, g.invh, GRID_G);
        int cy = cell_coord(s.y, g.y0, g.invh, GRID_G);
        int cz = cell_coord(s.z, g.z0, g.invh, GRID_G);
        int c = (cz * GRID_G + cy) * GRID_G + cx;
        int pos = g_cellstart3[c] + atomicAdd(&g_cursor3[c], 1);
        g_ssorted[pos] = s;
        g_sfp[pos] = fp[i / NSAMP];
    }
}

// ---------------- kernel F: fused forward + reverse + final ----------------
__global__ void __launch_bounds__(256) fused_nn_kernel(const float* __restrict__ fp,
                                                       float* __restrict__ out) {
    int b = blockIdx.x;
    int tid = threadIdx.x;

    if (b < FWD_WARP_BLOCKS) {
        // -------- forward: one warp per simplified barycenter --------
        int warp = (b * 256 + tid) >> 5;
        int lane = tid & 31;
        if (warp < N_SF) {
            GridGeom g = load_geom(g_bbox2, GRID_G2);
            float4 Q = g_sb[warp];
            float m2x = -2.0f * Q.x, m2y = -2.0f * Q.y, m2z = -2.0f * Q.z;
            int cx = cell_coord(Q.x, g.x0, g.invh, GRID_G2);
            int cy = cell_coord(Q.y, g.y0, g.invh, GRID_G2);
            int cz = cell_coord(Q.z, g.z0, g.invh, GRID_G2);
            const int G = GRID_G2;

            float best = 3.0e38f;
            for (int R = 0; R <= G; R++) {
                float bmin = best;
#pragma unroll
                for (int o = 16; o > 0; o >>= 1)
                    bmin = fminf(bmin, __shfl_xor_sync(0xffffffffu, bmin, o));
                if (R > 0) {
                    float lb = (float)(R - 1) * g.h;
                    if (bmin + Q.w <= lb * lb) break;
                }
                int zlo = max(cz - R, 0), zhi = min(cz + R, G - 1);
                int ylo = max(cy - R, 0), yhi = min(cy + R, G - 1);
                int xlo = max(cx - R, 0), xhi = min(cx + R, G - 1);
                for (int z = zlo; z <= zhi; z++) {
                    bool ze = (z == cz - R) || (z == cz + R);
                    for (int y = ylo; y <= yhi; y++) {
                        bool edge = ze || (y == cy - R) || (y == cy + R);
                        int rowbase = (z * G + y) * G;
                        if (edge) {
                            int p0 = __ldg(&g_cellstart2[rowbase + xlo]);
                            int p1 = __ldg(&g_cellstart2[rowbase + xhi + 1]);
                            for (int p = p0 + lane; p < p1; p += 32) {
                                float4 v = g_sorted2[p];
                                float t = fmaf(v.x, m2x, fmaf(v.y, m2y, fmaf(v.z, m2z, v.w)));
                                best = fminf(best, t);
                            }
                        } else {
                            int xa = cx - R, xb = cx + R;
                            if (xa >= 0) {
                                int c0 = rowbase + xa;
                                int p0 = __ldg(&g_cellstart2[c0]), p1 = __ldg(&g_cellstart2[c0 + 1]);
                                for (int p = p0 + lane; p < p1; p += 32) {
                                    float4 v = g_sorted2[p];
                                    float t = fmaf(v.x, m2x, fmaf(v.y, m2y, fmaf(v.z, m2z, v.w)));
                                    best = fminf(best, t);
                                }
                            }
                            if (xb <= G - 1) {
                                int c0 = rowbase + xb;
                                int p0 = __ldg(&g_cellstart2[c0]), p1 = __ldg(&g_cellstart2[c0 + 1]);
                                for (int p = p0 + lane; p < p1; p += 32) {
                                    float4 v = g_sorted2[p];
                                    float t = fmaf(v.x, m2x, fmaf(v.y, m2y, fmaf(v.z, m2z, v.w)));
                                    best = fminf(best, t);
                                }
                            }
                        }
                    }
                }
                if (zlo == 0 && ylo == 0 && xlo == 0 &&
                    zhi == G - 1 && yhi == G - 1 && xhi == G - 1) break;
            }
            float bmin = best;
#pragma unroll
            for (int o = 16; o > 0; o >>= 1)
                bmin = fminf(bmin, __shfl_xor_sync(0xffffffffu, bmin, o));
            if (lane == 0)
                g_minfwd[warp] = __float_as_uint(fmaxf(bmin + Q.w, 0.0f));
        }
    } else {
        // -------- reverse: one thread per cell-sorted sample --------
        int rb = b - FWD_WARP_BLOCKS;
        int j = rb * 256 + tid;

        float d = 0.0f;
        double contrib = 0.0;
        if (j < N_SAMPLES) {
            GridGeom g = load_geom(g_bbox, GRID_G);
            float4 s = g_ssorted[j];
            float d2 = shell_nn<GRID_G>(s.x, s.y, s.z, s.w, g, g_cellstart, g_sorted);
            d = sqrtf(d2);
            contrib = (double)(g_sfp[j] * d);
        }

        __shared__ double rsum[256];
        __shared__ float rmax[256];
        rsum[tid] = contrib;
        rmax[tid] = d;
        __syncthreads();
#pragma unroll
        for (int o = 128; o > 0; o >>= 1) {
            if (tid < o) {
                rsum[tid] += rsum[tid + o];
                rmax[tid] = fmaxf(rmax[tid], rmax[tid + o]);
            }
            __syncthreads();
        }
        if (tid == 0) {
            g_part[rb] = rsum[0];
            atomicMax(&g_maxbits, __float_as_uint(rmax[0]));
        }
    }

    // -------- completion: last block runs the final reduction --------
    __syncthreads();
    __threadfence();
    __shared__ unsigned s_rank;
    if (tid == 0) s_rank = atomicAdd(&g_done, 1u);
    __syncthreads();
    if (s_rank != FUSED_BLOCKS - 1) return;

    __shared__ double red[256];
    double fwd = 0.0, pen = 0.0, rev = 0.0;
    for (int i = tid; i < N_SF; i += 256) {
        float p = fp[i];
        float d2 = __uint_as_float(g_minfwd[i]);
        fwd += (double)(p * sqrtf(d2));
        pen += (double)(1.0f - p);
    }
    for (int k = tid; k < REV_BLOCKS; k += 256) rev += g_part[k];

    double totF, totP, totR;
    red[tid] = fwd; __syncthreads();
#pragma unroll
    for (int o = 128; o > 0; o >>= 1) { if (tid < o) red[tid] += red[tid + o]; __syncthreads(); }
    totF = red[0]; __syncthreads();
    red[tid] = pen; __syncthreads();
#pragma unroll
    for (int o = 128; o > 0; o >>= 1) { if (tid < o) red[tid] += red[tid + o]; __syncthreads(); }
    totP = red[0]; __syncthreads();
    red[tid] = rev; __syncthreads();
#pragma unroll
    for (int o = 128; o > 0; o >>= 1) { if (tid < o) red[tid] += red[tid + o]; __syncthreads(); }
    totR = red[0];

    if (tid == 0) {
        double maxd = (double)__uint_as_float(g_maxbits);
        double result = totF + 1e-4 * totP + totR / (maxd + 1e-8) * 0.1;
        out[0] = (float)result;
    }
}

// ---------------- launch ----------------
extern "C" void kernel_launch(void* const* d_in, const int* in_sizes, int n_in,
                              void* d_out, int out_size) {
    const float* ov = (const float*)d_in[0];
    const int*   of = (const int*)  d_in[1];
    const float* sv = (const float*)d_in[2];
    const int*   sf = (const int*)  d_in[3];
    const float* fp = (const float*)d_in[4];
    float* out = (float*)d_out;

    init_prep_kernel<<<(NCELLS + 255) / 256, 256>>>(ov, of, sv, sf);
    gen_count_kernel<<<GEN_BLOCKS, 256>>>(ov, sv, sf);
    scan1_kernel<<<3 * SCAN_BLOCKS, 1024>>>();
    scan3_kernel<<<3 * SCAN_BLOCKS, 1024>>>();
    scatter_kernel<<<GEN_BLOCKS, 256>>>(ov, fp);
    fused_nn_kernel<<<FUSED_BLOCKS, 256>>>(fp, out);
}